// round 3
// baseline (speedup 1.0000x reference)
#include <cuda_runtime.h>
#include <cuda_bf16.h>
#include <cuda_fp16.h>
#include <cstdint>

// Problem constants (fixed by the dataset)
#define NN_NODES 10000
#define NN_EDGES 120000
#define IN_W 6
#define WN 32
#define WK 256
#define DEPTH 4

// ---------------- scratch (device globals; no allocation allowed) ----------
__device__ __half       g_we [(size_t)NN_EDGES * WN * WN];    // 245 MB per-edge weight mats (fp16)
__device__ __nv_bfloat16 g_h1h[(size_t)NN_EDGES * (WK / 2)];  // edge MLP hidden 1 (bf16 hi)
__device__ __nv_bfloat16 g_h1l[(size_t)NN_EDGES * (WK / 2)];  // edge MLP hidden 1 (bf16 lo)
__device__ __nv_bfloat16 g_h2h[(size_t)NN_EDGES * WK];        // edge MLP hidden 2 (bf16 hi)
__device__ __nv_bfloat16 g_h2l[(size_t)NN_EDGES * WK];        // edge MLP hidden 2 (bf16 lo)
__device__ __nv_bfloat16 g_k2h[(WK / 2) * WK];
__device__ __nv_bfloat16 g_k2l[(WK / 2) * WK];
__device__ __nv_bfloat16 g_k3h[WK * WN * WN];
__device__ __nv_bfloat16 g_k3l[WK * WN * WN];
__device__ float g_h   [(size_t)NN_NODES * WN];               // node features
__device__ float g_aggr[(size_t)NN_NODES * WN];               // scatter accumulator
__device__ float g_deg [NN_NODES];                            // in-degree (float)

// ============================================================================
// bf16-split tensor-core GEMM: C = act(A@B + bias)
// A [M,K] row-major as (Ah,Al) bf16; B [K,N] row-major as (Bh,Bl) bf16.
// C ≈ Ah*Bh + Al*Bh + Ah*Bl  (fp32 accum; dropped Al*Bl term is ~2^-18 rel).
// Block tile 128x128, BK=32, 256 threads (8 warps, 2x4), warp tile 64x32.
// cp.async 2-stage pipeline; ldmatrix with padded smem (conflict-free).
// outMode: 0 = fp32 (Cf), 1 = bf16 hi/lo split (Ch,Cl), 2 = fp16 (Cp)
// ============================================================================

#define SA_PAD 40
#define SB_PAD 136
#define AH_OFF 0
#define AL_OFF (128 * SA_PAD)               // 5120
#define BH_OFF (2 * 128 * SA_PAD)           // 10240
#define BL_OFF (BH_OFF + 32 * SB_PAD)       // 14592
#define BUF_H  (BL_OFF + 32 * SB_PAD)       // 18944 halves per buffer
#define SMEM_BYTES (2 * BUF_H * 2)          // 75776 bytes

__device__ __forceinline__ void cp16(uint32_t dst, const void* src, int sbytes) {
    asm volatile("cp.async.cg.shared.global [%0], [%1], 16, %2;\n"
                 :: "r"(dst), "l"(src), "r"(sbytes));
}
__device__ __forceinline__ void ldsm_x4(uint32_t* r, uint32_t addr) {
    asm volatile("ldmatrix.sync.aligned.m8n8.x4.shared.b16 {%0,%1,%2,%3}, [%4];"
                 : "=r"(r[0]), "=r"(r[1]), "=r"(r[2]), "=r"(r[3]) : "r"(addr));
}
__device__ __forceinline__ void ldsm_x2t(uint32_t& b0, uint32_t& b1, uint32_t addr) {
    asm volatile("ldmatrix.sync.aligned.m8n8.x2.trans.shared.b16 {%0,%1}, [%2];"
                 : "=r"(b0), "=r"(b1) : "r"(addr));
}
__device__ __forceinline__ void mma16816(float* c, const uint32_t* a, uint32_t b0, uint32_t b1) {
    asm volatile("mma.sync.aligned.m16n8k16.row.col.f32.bf16.bf16.f32 "
                 "{%0,%1,%2,%3}, {%4,%5,%6,%7}, {%8,%9}, {%0,%1,%2,%3};"
                 : "+f"(c[0]), "+f"(c[1]), "+f"(c[2]), "+f"(c[3])
                 : "r"(a[0]), "r"(a[1]), "r"(a[2]), "r"(a[3]), "r"(b0), "r"(b1));
}

__global__ __launch_bounds__(256, 1)
void mma_split_gemm(const __nv_bfloat16* __restrict__ Ah, const __nv_bfloat16* __restrict__ Al,
                    const __nv_bfloat16* __restrict__ Bh, const __nv_bfloat16* __restrict__ Bl,
                    const float* __restrict__ bias,
                    float* __restrict__ Cf, __nv_bfloat16* __restrict__ Ch, __nv_bfloat16* __restrict__ Cl,
                    __half* __restrict__ Cp,
                    int M, int N, int K, int doRelu, int outMode)
{
    extern __shared__ __nv_bfloat16 smem[];
    const int tid  = threadIdx.x;
    const int lane = tid & 31;
    const int wid  = tid >> 5;
    const int bm = blockIdx.y * 128;
    const int bn = blockIdx.x * 128;
    const int warp_m = (wid & 1) * 64;
    const int warp_n = (wid >> 1) * 32;

    uint32_t su = (uint32_t)__cvta_generic_to_shared(smem);

    float C[4][4][4];
#pragma unroll
    for (int mt = 0; mt < 4; mt++)
#pragma unroll
        for (int nt = 0; nt < 4; nt++)
#pragma unroll
            for (int q = 0; q < 4; q++) C[mt][nt][q] = 0.f;

    const int nk = K / 32;

    auto load_tile = [&](int kt, int buf) {
        const int k0 = kt * 32;
        const uint32_t sbase = su + (uint32_t)buf * BUF_H * 2;
#pragma unroll
        for (int t = 0; t < 4; t++) {
            int cid = tid + t * 256;
            int mat = cid >> 9;
            int rr  = (cid & 511) >> 2;
            int c8  = (cid & 3) * 8;
            int gr  = bm + rr;
            int ok  = (gr < M) ? 16 : 0;
            const __nv_bfloat16* src = (mat ? Al : Ah) + (size_t)(ok ? gr : 0) * K + k0 + c8;
            uint32_t dst = sbase + (uint32_t)((mat ? AL_OFF : AH_OFF) + rr * SA_PAD + c8) * 2;
            cp16(dst, src, ok);
        }
#pragma unroll
        for (int t = 0; t < 4; t++) {
            int cid = tid + t * 256;
            int mat = cid >> 9;
            int rr  = (cid & 511) >> 4;
            int c8  = (cid & 15) * 8;
            const __nv_bfloat16* src = (mat ? Bl : Bh) + (size_t)(k0 + rr) * N + bn + c8;
            uint32_t dst = sbase + (uint32_t)((mat ? BL_OFF : BH_OFF) + rr * SB_PAD + c8) * 2;
            cp16(dst, src, 16);
        }
    };

    load_tile(0, 0);
    asm volatile("cp.async.commit_group;\n" ::: "memory");

    for (int i = 0; i < nk; i++) {
        const int buf = i & 1;
        if (i + 1 < nk) {
            load_tile(i + 1, buf ^ 1);
            asm volatile("cp.async.commit_group;\n" ::: "memory");
            asm volatile("cp.async.wait_group 1;\n" ::: "memory");
        } else {
            asm volatile("cp.async.wait_group 0;\n" ::: "memory");
        }
        __syncthreads();

        const uint32_t aH = su + (uint32_t)(buf * BUF_H + AH_OFF) * 2;
        const uint32_t aL = su + (uint32_t)(buf * BUF_H + AL_OFF) * 2;
        const uint32_t bH = su + (uint32_t)(buf * BUF_H + BH_OFF) * 2;
        const uint32_t bL = su + (uint32_t)(buf * BUF_H + BL_OFF) * 2;

        const int arow = lane & 15;
        const int acol = (lane >> 4) * 8;
        const int brow = lane & 15;

#pragma unroll
        for (int ks = 0; ks < 32; ks += 16) {
            uint32_t ah[4][4], al[4][4];
#pragma unroll
            for (int mt = 0; mt < 4; mt++) {
                uint32_t off = (uint32_t)((warp_m + mt * 16 + arow) * SA_PAD + ks + acol) * 2;
                ldsm_x4(ah[mt], aH + off);
                ldsm_x4(al[mt], aL + off);
            }
#pragma unroll
            for (int nt = 0; nt < 4; nt++) {
                uint32_t boff = (uint32_t)((ks + brow) * SB_PAD + warp_n + nt * 8) * 2;
                uint32_t bh0, bh1, bl0, bl1;
                ldsm_x2t(bh0, bh1, bH + boff);
                ldsm_x2t(bl0, bl1, bL + boff);
#pragma unroll
                for (int mt = 0; mt < 4; mt++) {
                    mma16816(C[mt][nt], ah[mt], bh0, bh1);
                    mma16816(C[mt][nt], al[mt], bh0, bh1);
                    mma16816(C[mt][nt], ah[mt], bl0, bl1);
                }
            }
        }
        __syncthreads();
    }

    // --- epilogue ---------------------------------------------------------------
#pragma unroll
    for (int mt = 0; mt < 4; mt++) {
#pragma unroll
        for (int nt = 0; nt < 4; nt++) {
            int r0  = bm + warp_m + mt * 16 + (lane >> 2);
            int col = bn + warp_n + nt * 8 + (lane & 3) * 2;
            float b0 = bias[col], b1 = bias[col + 1];
            float v0 = C[mt][nt][0] + b0;
            float v1 = C[mt][nt][1] + b1;
            float v2 = C[mt][nt][2] + b0;
            float v3 = C[mt][nt][3] + b1;
            if (doRelu) {
                v0 = fmaxf(v0, 0.f); v1 = fmaxf(v1, 0.f);
                v2 = fmaxf(v2, 0.f); v3 = fmaxf(v3, 0.f);
            }
            if (outMode == 1) {
                if (r0 < M) {
                    __nv_bfloat16 h0 = __float2bfloat16(v0), h1 = __float2bfloat16(v1);
                    __nv_bfloat162 hp; hp.x = h0; hp.y = h1;
                    __nv_bfloat162 lp; lp.x = __float2bfloat16(v0 - __bfloat162float(h0));
                    lp.y = __float2bfloat16(v1 - __bfloat162float(h1));
                    *reinterpret_cast<__nv_bfloat162*>(&Ch[(size_t)r0 * N + col]) = hp;
                    *reinterpret_cast<__nv_bfloat162*>(&Cl[(size_t)r0 * N + col]) = lp;
                }
                if (r0 + 8 < M) {
                    __nv_bfloat16 h2 = __float2bfloat16(v2), h3 = __float2bfloat16(v3);
                    __nv_bfloat162 hp; hp.x = h2; hp.y = h3;
                    __nv_bfloat162 lp; lp.x = __float2bfloat16(v2 - __bfloat162float(h2));
                    lp.y = __float2bfloat16(v3 - __bfloat162float(h3));
                    *reinterpret_cast<__nv_bfloat162*>(&Ch[(size_t)(r0 + 8) * N + col]) = hp;
                    *reinterpret_cast<__nv_bfloat162*>(&Cl[(size_t)(r0 + 8) * N + col]) = lp;
                }
            } else if (outMode == 2) {
                if (r0 < M) {
                    __half2 p; p.x = __float2half(v0); p.y = __float2half(v1);
                    *reinterpret_cast<__half2*>(&Cp[(size_t)r0 * N + col]) = p;
                }
                if (r0 + 8 < M) {
                    __half2 p; p.x = __float2half(v2); p.y = __float2half(v3);
                    *reinterpret_cast<__half2*>(&Cp[(size_t)(r0 + 8) * N + col]) = p;
                }
            } else {
                if (r0 < M) {
                    float2 p; p.x = v0; p.y = v1;
                    *reinterpret_cast<float2*>(&Cf[(size_t)r0 * N + col]) = p;
                }
                if (r0 + 8 < M) {
                    float2 p; p.x = v2; p.y = v3;
                    *reinterpret_cast<float2*>(&Cf[(size_t)(r0 + 8) * N + col]) = p;
                }
            }
        }
    }
}

// ---------------- small kernels --------------------------------------------

__global__ void split_kernel(const float* __restrict__ in, __nv_bfloat16* __restrict__ hi,
                             __nv_bfloat16* __restrict__ lo, int n)
{
    int i = blockIdx.x * blockDim.x + threadIdx.x;
    if (i < n) {
        float v = in[i];
        __nv_bfloat16 h = __float2bfloat16(v);
        hi[i] = h;
        lo[i] = __float2bfloat16(v - __bfloat162float(h));
    }
}

// h1 = relu(ea @ k1_w + k1_b), written split. One block (128 thr) per edge.
__global__ __launch_bounds__(128)
void edge_fc1_kernel(const float* __restrict__ ea, const float* __restrict__ w,
                     const float* __restrict__ b, int E)
{
    int e = blockIdx.x, tid = threadIdx.x;
    __shared__ float a[IN_W];
    if (tid < IN_W) a[tid] = ea[(size_t)e * IN_W + tid];
    __syncthreads();
    float acc = b[tid];
#pragma unroll
    for (int i = 0; i < IN_W; i++) acc = fmaf(a[i], w[i * (WK / 2) + tid], acc);
    acc = fmaxf(acc, 0.f);
    __nv_bfloat16 h = __float2bfloat16(acc);
    g_h1h[(size_t)e * (WK / 2) + tid] = h;
    g_h1l[(size_t)e * (WK / 2) + tid] = __float2bfloat16(acc - __bfloat162float(h));
}

__global__ void deg_kernel(const int* __restrict__ dst, int E)
{
    int e = blockIdx.x * blockDim.x + threadIdx.x;
    if (e < E) atomicAdd(&g_deg[dst[e]], 1.f);
}

// h = x @ fc1_w + fc1_b  (one warp per node)
__global__ __launch_bounds__(256)
void fc1_kernel(const float* __restrict__ x, const float* __restrict__ w,
                const float* __restrict__ b, int N)
{
    int warp = threadIdx.x >> 5, lane = threadIdx.x & 31;
    int n = blockIdx.x * 8 + warp;
    if (n >= N) return;
    float xv = (lane < IN_W) ? x[(size_t)n * IN_W + lane] : 0.f;
    float acc = b[lane];
#pragma unroll
    for (int i = 0; i < IN_W; i++) {
        float xi = __shfl_sync(0xffffffffu, xv, i);
        acc = fmaf(xi, w[i * WN + lane], acc);
    }
    g_h[(size_t)n * WN + lane] = acc;
}

// per-edge matvec msg = h[src] @ w_e (fp16 weights), scattered to aggr[dst]
__global__ __launch_bounds__(256)
void msg_scatter_kernel(const int* __restrict__ src, const int* __restrict__ dst, int E)
{
    int warp = threadIdx.x >> 5, lane = threadIdx.x & 31;
    int e = blockIdx.x * 8 + warp;
    if (e >= E) return;
    int s = src[e], d = dst[e];
    float hv = g_h[(size_t)s * WN + lane];
    const __half* w = &g_we[(size_t)e * WN * WN];
    float acc = 0.f;
#pragma unroll
    for (int i = 0; i < WN; i++) {
        float hi = __shfl_sync(0xffffffffu, hv, i);
        acc = fmaf(hi, __half2float(w[i * WN + lane]), acc);
    }
    atomicAdd(&g_aggr[(size_t)d * WN + lane], acc);
}

// h = [relu]( aggr/denom + h @ root_w + conv_b )   (in place, one warp/node)
__global__ __launch_bounds__(256)
void combine_kernel(const float* __restrict__ root_w, const float* __restrict__ conv_b,
                    int N, int doRelu)
{
    __shared__ float rw[WN * WN];
    __shared__ float cb[WN];
    int tid = threadIdx.x;
    for (int i = tid; i < WN * WN; i += blockDim.x) rw[i] = root_w[i];
    if (tid < WN) cb[tid] = conv_b[tid];
    __syncthreads();

    int warp = tid >> 5, lane = tid & 31;
    int n = blockIdx.x * 8 + warp;
    if (n >= N) return;
    float hv = g_h[(size_t)n * WN + lane];
    float denom = fmaxf(g_deg[n], 1.f);
    float acc = g_aggr[(size_t)n * WN + lane] / denom + cb[lane];
#pragma unroll
    for (int i = 0; i < WN; i++) {
        float hi = __shfl_sync(0xffffffffu, hv, i);
        acc = fmaf(hi, rw[i * WN + lane], acc);
    }
    if (doRelu) acc = fmaxf(acc, 0.f);
    g_h[(size_t)n * WN + lane] = acc;
}

// out = relu(h @ fc2_w + fc2_b) @ fc3_w + fc3_b   (one 128-thread block/node)
__global__ __launch_bounds__(128)
void head_kernel(const float* __restrict__ fc2_w, const float* __restrict__ fc2_b,
                 const float* __restrict__ fc3_w, const float* __restrict__ fc3_b,
                 float* __restrict__ out)
{
    int n = blockIdx.x, tid = threadIdx.x;
    __shared__ float sh[WN];
    __shared__ float red[4];
    if (tid < WN) sh[tid] = g_h[(size_t)n * WN + tid];
    __syncthreads();
    float a = fc2_b[tid];
#pragma unroll
    for (int i = 0; i < WN; i++) a = fmaf(sh[i], fc2_w[i * 128 + tid], a);
    a = fmaxf(a, 0.f) * fc3_w[tid];
#pragma unroll
    for (int o = 16; o; o >>= 1) a += __shfl_xor_sync(0xffffffffu, a, o);
    if ((tid & 31) == 0) red[tid >> 5] = a;
    __syncthreads();
    if (tid == 0) out[n] = red[0] + red[1] + red[2] + red[3] + fc3_b[0];
}

// ---------------- launch ----------------------------------------------------
extern "C" void kernel_launch(void* const* d_in, const int* in_sizes, int n_in,
                              void* d_out, int out_size)
{
    const float* x      = (const float*)d_in[0];
    const int*   ei     = (const int*)  d_in[1];
    const float* ea     = (const float*)d_in[2];
    const float* fc1_w  = (const float*)d_in[3];
    const float* fc1_b  = (const float*)d_in[4];
    const float* k1_w   = (const float*)d_in[5];
    const float* k1_b   = (const float*)d_in[6];
    const float* k2_w   = (const float*)d_in[7];
    const float* k2_b   = (const float*)d_in[8];
    const float* k3_w   = (const float*)d_in[9];
    const float* k3_b   = (const float*)d_in[10];
    const float* root_w = (const float*)d_in[11];
    const float* conv_b = (const float*)d_in[12];
    const float* fc2_w  = (const float*)d_in[13];
    const float* fc2_b  = (const float*)d_in[14];
    const float* fc3_w  = (const float*)d_in[15];
    const float* fc3_b  = (const float*)d_in[16];
    float* out = (float*)d_out;

    const int N = in_sizes[0] / IN_W;
    const int E = in_sizes[1] / 2;
    const int* src = ei;
    const int* dst = ei + E;

    float *aggr, *deg;
    __half *we;
    __nv_bfloat16 *h1h, *h1l, *h2h, *h2l, *k2h, *k2l, *k3h, *k3l;
    cudaGetSymbolAddress((void**)&we,   g_we);
    cudaGetSymbolAddress((void**)&aggr, g_aggr);
    cudaGetSymbolAddress((void**)&deg,  g_deg);
    cudaGetSymbolAddress((void**)&h1h,  g_h1h);
    cudaGetSymbolAddress((void**)&h1l,  g_h1l);
    cudaGetSymbolAddress((void**)&h2h,  g_h2h);
    cudaGetSymbolAddress((void**)&h2l,  g_h2l);
    cudaGetSymbolAddress((void**)&k2h,  g_k2h);
    cudaGetSymbolAddress((void**)&k2l,  g_k2l);
    cudaGetSymbolAddress((void**)&k3h,  g_k3h);
    cudaGetSymbolAddress((void**)&k3l,  g_k3l);

    static bool attr_done = false;
    if (!attr_done) {
        cudaFuncSetAttribute(mma_split_gemm, cudaFuncAttributeMaxDynamicSharedMemorySize, SMEM_BYTES);
        attr_done = true;
    }

    // --- launch order arranged so GEMM3 lands at kernel-launch index 5 for ncu ---
    // edge MLP layer 1 + weight splits
    edge_fc1_kernel<<<E, WK / 2>>>(ea, k1_w, k1_b, E);                                   // 0
    split_kernel<<<((WK / 2) * WK + 255) / 256, 256>>>(k2_w, k2h, k2l, (WK / 2) * WK);   // 1
    split_kernel<<<(WK * WN * WN + 255) / 256, 256>>>(k3_w, k3h, k3l, WK * WN * WN);     // 2

    // GEMM2: h2 = relu(h1 @ k2_w + k2_b), split bf16 out.  M=E, N=256, K=128
    {
        dim3 grid(WK / 128, (E + 127) / 128);
        mma_split_gemm<<<grid, 256, SMEM_BYTES>>>(h1h, h1l, k2h, k2l, k2_b,              // 3
                                                  nullptr, h2h, h2l, nullptr, E, WK, WK / 2, 1, 1);
    }
    // node init: h = x @ fc1_w + fc1_b
    fc1_kernel<<<(N + 7) / 8, 256>>>(x, fc1_w, fc1_b, N);                                // 4
    // GEMM3: w_e = h2 @ k3_w + k3_b, fp16 out.  M=E, N=1024, K=256
    {
        dim3 grid(WN * WN / 128, (E + 127) / 128);
        mma_split_gemm<<<grid, 256, SMEM_BYTES>>>(h2h, h2l, k3h, k3l, k3_b,              // 5
                                                  nullptr, nullptr, nullptr, we, E, WN * WN, WK, 0, 2);
    }

    // in-degree (needed only by combine)
    cudaMemsetAsync(deg, 0, (size_t)N * sizeof(float));
    deg_kernel<<<(E + 255) / 256, 256>>>(dst, E);

    // message passing
    for (int d = 0; d < DEPTH; d++) {
        cudaMemsetAsync(aggr, 0, (size_t)N * WN * sizeof(float));
        msg_scatter_kernel<<<(E + 7) / 8, 256>>>(src, dst, E);
        combine_kernel<<<(N + 7) / 8, 256>>>(root_w, conv_b, N, d != DEPTH - 1 ? 1 : 0);
    }

    // head
    head_kernel<<<N, 128>>>(fc2_w, fc2_b, fc3_w, fc3_b, out);
}

// round 4
// speedup vs baseline: 1.5286x; 1.5286x over previous
#include <cuda_runtime.h>
#include <cuda_bf16.h>
#include <cuda_fp16.h>
#include <cstdint>

// Problem constants (fixed by the dataset)
#define NN_NODES 10000
#define NN_EDGES 120000
#define IN_W 6
#define WN 32
#define WK 256
#define DEPTH 4

// ---------------- scratch (device globals; no allocation allowed) ----------
__device__ __half       g_we [(size_t)NN_EDGES * WN * WN];    // 245 MB per-edge weight mats (fp16)
__device__ __nv_bfloat16 g_h1h[(size_t)NN_EDGES * (WK / 2)];  // edge MLP hidden 1 (bf16 hi)
__device__ __nv_bfloat16 g_h1l[(size_t)NN_EDGES * (WK / 2)];  // edge MLP hidden 1 (bf16 lo)
__device__ __nv_bfloat16 g_h2h[(size_t)NN_EDGES * WK];        // edge MLP hidden 2 (bf16 hi)
__device__ __nv_bfloat16 g_h2l[(size_t)NN_EDGES * WK];        // edge MLP hidden 2 (bf16 lo)
__device__ __nv_bfloat16 g_k2h[(WK / 2) * WK];
__device__ __nv_bfloat16 g_k2l[(WK / 2) * WK];
__device__ __nv_bfloat16 g_k3h[WK * WN * WN];
__device__ __nv_bfloat16 g_k3l[WK * WN * WN];
__device__ float g_h   [(size_t)NN_NODES * WN];               // node features
__device__ float g_aggr[(size_t)NN_NODES * WN];               // scatter accumulator
__device__ float g_deg [NN_NODES];                            // in-degree (float)

// ============================================================================
// bf16-split tensor-core GEMM (same as R2/R3): C = act(A@B + bias)
// ============================================================================

#define SA_PAD 40
#define SB_PAD 136
#define AH_OFF 0
#define AL_OFF (128 * SA_PAD)
#define BH_OFF (2 * 128 * SA_PAD)
#define BL_OFF (BH_OFF + 32 * SB_PAD)
#define BUF_H  (BL_OFF + 32 * SB_PAD)
#define SMEM_BYTES (2 * BUF_H * 2)

__device__ __forceinline__ void cp16(uint32_t dst, const void* src, int sbytes) {
    asm volatile("cp.async.cg.shared.global [%0], [%1], 16, %2;\n"
                 :: "r"(dst), "l"(src), "r"(sbytes));
}
__device__ __forceinline__ void ldsm_x4(uint32_t* r, uint32_t addr) {
    asm volatile("ldmatrix.sync.aligned.m8n8.x4.shared.b16 {%0,%1,%2,%3}, [%4];"
                 : "=r"(r[0]), "=r"(r[1]), "=r"(r[2]), "=r"(r[3]) : "r"(addr));
}
__device__ __forceinline__ void ldsm_x2t(uint32_t& b0, uint32_t& b1, uint32_t addr) {
    asm volatile("ldmatrix.sync.aligned.m8n8.x2.trans.shared.b16 {%0,%1}, [%2];"
                 : "=r"(b0), "=r"(b1) : "r"(addr));
}
__device__ __forceinline__ void mma16816(float* c, const uint32_t* a, uint32_t b0, uint32_t b1) {
    asm volatile("mma.sync.aligned.m16n8k16.row.col.f32.bf16.bf16.f32 "
                 "{%0,%1,%2,%3}, {%4,%5,%6,%7}, {%8,%9}, {%0,%1,%2,%3};"
                 : "+f"(c[0]), "+f"(c[1]), "+f"(c[2]), "+f"(c[3])
                 : "r"(a[0]), "r"(a[1]), "r"(a[2]), "r"(a[3]), "r"(b0), "r"(b1));
}

__global__ __launch_bounds__(256, 1)
void mma_split_gemm(const __nv_bfloat16* __restrict__ Ah, const __nv_bfloat16* __restrict__ Al,
                    const __nv_bfloat16* __restrict__ Bh, const __nv_bfloat16* __restrict__ Bl,
                    const float* __restrict__ bias,
                    float* __restrict__ Cf, __nv_bfloat16* __restrict__ Ch, __nv_bfloat16* __restrict__ Cl,
                    __half* __restrict__ Cp,
                    int M, int N, int K, int doRelu, int outMode)
{
    extern __shared__ __nv_bfloat16 smem[];
    const int tid  = threadIdx.x;
    const int lane = tid & 31;
    const int wid  = tid >> 5;
    const int bm = blockIdx.y * 128;
    const int bn = blockIdx.x * 128;
    const int warp_m = (wid & 1) * 64;
    const int warp_n = (wid >> 1) * 32;

    uint32_t su = (uint32_t)__cvta_generic_to_shared(smem);

    float C[4][4][4];
#pragma unroll
    for (int mt = 0; mt < 4; mt++)
#pragma unroll
        for (int nt = 0; nt < 4; nt++)
#pragma unroll
            for (int q = 0; q < 4; q++) C[mt][nt][q] = 0.f;

    const int nk = K / 32;

    auto load_tile = [&](int kt, int buf) {
        const int k0 = kt * 32;
        const uint32_t sbase = su + (uint32_t)buf * BUF_H * 2;
#pragma unroll
        for (int t = 0; t < 4; t++) {
            int cid = tid + t * 256;
            int mat = cid >> 9;
            int rr  = (cid & 511) >> 2;
            int c8  = (cid & 3) * 8;
            int gr  = bm + rr;
            int ok  = (gr < M) ? 16 : 0;
            const __nv_bfloat16* src = (mat ? Al : Ah) + (size_t)(ok ? gr : 0) * K + k0 + c8;
            uint32_t dst = sbase + (uint32_t)((mat ? AL_OFF : AH_OFF) + rr * SA_PAD + c8) * 2;
            cp16(dst, src, ok);
        }
#pragma unroll
        for (int t = 0; t < 4; t++) {
            int cid = tid + t * 256;
            int mat = cid >> 9;
            int rr  = (cid & 511) >> 4;
            int c8  = (cid & 15) * 8;
            const __nv_bfloat16* src = (mat ? Bl : Bh) + (size_t)(k0 + rr) * N + bn + c8;
            uint32_t dst = sbase + (uint32_t)((mat ? BL_OFF : BH_OFF) + rr * SB_PAD + c8) * 2;
            cp16(dst, src, 16);
        }
    };

    load_tile(0, 0);
    asm volatile("cp.async.commit_group;\n" ::: "memory");

    for (int i = 0; i < nk; i++) {
        const int buf = i & 1;
        if (i + 1 < nk) {
            load_tile(i + 1, buf ^ 1);
            asm volatile("cp.async.commit_group;\n" ::: "memory");
            asm volatile("cp.async.wait_group 1;\n" ::: "memory");
        } else {
            asm volatile("cp.async.wait_group 0;\n" ::: "memory");
        }
        __syncthreads();

        const uint32_t aH = su + (uint32_t)(buf * BUF_H + AH_OFF) * 2;
        const uint32_t aL = su + (uint32_t)(buf * BUF_H + AL_OFF) * 2;
        const uint32_t bH = su + (uint32_t)(buf * BUF_H + BH_OFF) * 2;
        const uint32_t bL = su + (uint32_t)(buf * BUF_H + BL_OFF) * 2;

        const int arow = lane & 15;
        const int acol = (lane >> 4) * 8;
        const int brow = lane & 15;

#pragma unroll
        for (int ks = 0; ks < 32; ks += 16) {
            uint32_t ah[4][4], al[4][4];
#pragma unroll
            for (int mt = 0; mt < 4; mt++) {
                uint32_t off = (uint32_t)((warp_m + mt * 16 + arow) * SA_PAD + ks + acol) * 2;
                ldsm_x4(ah[mt], aH + off);
                ldsm_x4(al[mt], aL + off);
            }
#pragma unroll
            for (int nt = 0; nt < 4; nt++) {
                uint32_t boff = (uint32_t)((ks + brow) * SB_PAD + warp_n + nt * 8) * 2;
                uint32_t bh0, bh1, bl0, bl1;
                ldsm_x2t(bh0, bh1, bH + boff);
                ldsm_x2t(bl0, bl1, bL + boff);
#pragma unroll
                for (int mt = 0; mt < 4; mt++) {
                    mma16816(C[mt][nt], ah[mt], bh0, bh1);
                    mma16816(C[mt][nt], al[mt], bh0, bh1);
                    mma16816(C[mt][nt], ah[mt], bl0, bl1);
                }
            }
        }
        __syncthreads();
    }

#pragma unroll
    for (int mt = 0; mt < 4; mt++) {
#pragma unroll
        for (int nt = 0; nt < 4; nt++) {
            int r0  = bm + warp_m + mt * 16 + (lane >> 2);
            int col = bn + warp_n + nt * 8 + (lane & 3) * 2;
            float b0 = bias[col], b1 = bias[col + 1];
            float v0 = C[mt][nt][0] + b0;
            float v1 = C[mt][nt][1] + b1;
            float v2 = C[mt][nt][2] + b0;
            float v3 = C[mt][nt][3] + b1;
            if (doRelu) {
                v0 = fmaxf(v0, 0.f); v1 = fmaxf(v1, 0.f);
                v2 = fmaxf(v2, 0.f); v3 = fmaxf(v3, 0.f);
            }
            if (outMode == 1) {
                if (r0 < M) {
                    __nv_bfloat16 h0 = __float2bfloat16(v0), h1 = __float2bfloat16(v1);
                    __nv_bfloat162 hp; hp.x = h0; hp.y = h1;
                    __nv_bfloat162 lp; lp.x = __float2bfloat16(v0 - __bfloat162float(h0));
                    lp.y = __float2bfloat16(v1 - __bfloat162float(h1));
                    *reinterpret_cast<__nv_bfloat162*>(&Ch[(size_t)r0 * N + col]) = hp;
                    *reinterpret_cast<__nv_bfloat162*>(&Cl[(size_t)r0 * N + col]) = lp;
                }
                if (r0 + 8 < M) {
                    __nv_bfloat16 h2 = __float2bfloat16(v2), h3 = __float2bfloat16(v3);
                    __nv_bfloat162 hp; hp.x = h2; hp.y = h3;
                    __nv_bfloat162 lp; lp.x = __float2bfloat16(v2 - __bfloat162float(h2));
                    lp.y = __float2bfloat16(v3 - __bfloat162float(h3));
                    *reinterpret_cast<__nv_bfloat162*>(&Ch[(size_t)(r0 + 8) * N + col]) = hp;
                    *reinterpret_cast<__nv_bfloat162*>(&Cl[(size_t)(r0 + 8) * N + col]) = lp;
                }
            } else if (outMode == 2) {
                if (r0 < M) {
                    __half2 p; p.x = __float2half(v0); p.y = __float2half(v1);
                    *reinterpret_cast<__half2*>(&Cp[(size_t)r0 * N + col]) = p;
                }
                if (r0 + 8 < M) {
                    __half2 p; p.x = __float2half(v2); p.y = __float2half(v3);
                    *reinterpret_cast<__half2*>(&Cp[(size_t)(r0 + 8) * N + col]) = p;
                }
            } else {
                if (r0 < M) {
                    float2 p; p.x = v0; p.y = v1;
                    *reinterpret_cast<float2*>(&Cf[(size_t)r0 * N + col]) = p;
                }
                if (r0 + 8 < M) {
                    float2 p; p.x = v2; p.y = v3;
                    *reinterpret_cast<float2*>(&Cf[(size_t)(r0 + 8) * N + col]) = p;
                }
            }
        }
    }
}

// ---------------- small kernels --------------------------------------------

__global__ void split_kernel(const float* __restrict__ in, __nv_bfloat16* __restrict__ hi,
                             __nv_bfloat16* __restrict__ lo, int n)
{
    int i = blockIdx.x * blockDim.x + threadIdx.x;
    if (i < n) {
        float v = in[i];
        __nv_bfloat16 h = __float2bfloat16(v);
        hi[i] = h;
        lo[i] = __float2bfloat16(v - __bfloat162float(h));
    }
}

// h1 = relu(ea @ k1_w + k1_b), written split. 256 threads = 2 edges per block.
__global__ __launch_bounds__(256)
void edge_fc1_kernel(const float* __restrict__ ea, const float* __restrict__ w,
                     const float* __restrict__ b, int E)
{
    int sub = threadIdx.x >> 7;                 // 0/1: which edge in block
    int tid = threadIdx.x & 127;
    int e = blockIdx.x * 2 + sub;
    if (e >= E) return;
    __shared__ float a[2][IN_W];
    if (tid < IN_W) a[sub][tid] = ea[(size_t)e * IN_W + tid];
    __syncthreads();
    float acc = b[tid];
#pragma unroll
    for (int i = 0; i < IN_W; i++) acc = fmaf(a[sub][i], w[i * (WK / 2) + tid], acc);
    acc = fmaxf(acc, 0.f);
    __nv_bfloat16 h = __float2bfloat16(acc);
    g_h1h[(size_t)e * (WK / 2) + tid] = h;
    g_h1l[(size_t)e * (WK / 2) + tid] = __float2bfloat16(acc - __bfloat162float(h));
}

__global__ void deg_kernel(const int* __restrict__ dst, int E)
{
    int e = blockIdx.x * blockDim.x + threadIdx.x;
    if (e < E) atomicAdd(&g_deg[dst[e]], 1.f);
}

// h = x @ fc1_w + fc1_b  (one warp per node)
__global__ __launch_bounds__(256)
void fc1_kernel(const float* __restrict__ x, const float* __restrict__ w,
                const float* __restrict__ b, int N)
{
    int warp = threadIdx.x >> 5, lane = threadIdx.x & 31;
    int n = blockIdx.x * 8 + warp;
    if (n >= N) return;
    float xv = (lane < IN_W) ? x[(size_t)n * IN_W + lane] : 0.f;
    float acc = b[lane];
#pragma unroll
    for (int i = 0; i < IN_W; i++) {
        float xi = __shfl_sync(0xffffffffu, xv, i);
        acc = fmaf(xi, w[i * WN + lane], acc);
    }
    g_h[(size_t)n * WN + lane] = acc;
}

// per-edge matvec msg = h[src] @ w_e (fp16), scattered to aggr[dst].
// Vectorized: lane = 16*r + j handles rows {i+r} and output cols {2j, 2j+1}.
// Each iteration the warp loads one full 128B line (2 matrix rows).
__global__ __launch_bounds__(256)
void msg_scatter_kernel(const int* __restrict__ src, const int* __restrict__ dst, int E)
{
    int warp = threadIdx.x >> 5, lane = threadIdx.x & 31;
    int e = blockIdx.x * 8 + warp;
    if (e >= E) return;
    int s = src[e], d = dst[e];
    int j = lane & 15;          // output col pair
    int r = lane >> 4;          // row parity
    float hv = g_h[(size_t)s * WN + lane];
    const __half2* w2 = reinterpret_cast<const __half2*>(&g_we[(size_t)e * WN * WN]);
    float ax = 0.f, ay = 0.f;
#pragma unroll
    for (int i = 0; i < WN; i += 2) {
        float hi = __shfl_sync(0xffffffffu, hv, i + r);
        float2 wf = __half22float2(w2[(i + r) * 16 + j]);
        ax = fmaf(hi, wf.x, ax);
        ay = fmaf(hi, wf.y, ay);
    }
    ax += __shfl_xor_sync(0xffffffffu, ax, 16);
    ay += __shfl_xor_sync(0xffffffffu, ay, 16);
    if (lane < 16) {
        atomicAdd(&g_aggr[(size_t)d * WN + 2 * j],     ax);
        atomicAdd(&g_aggr[(size_t)d * WN + 2 * j + 1], ay);
    }
}

// h = [relu]( aggr/denom + h @ root_w + conv_b )   (in place, one warp/node)
__global__ __launch_bounds__(256)
void combine_kernel(const float* __restrict__ root_w, const float* __restrict__ conv_b,
                    int N, int doRelu)
{
    __shared__ float rw[WN * WN];
    __shared__ float cb[WN];
    int tid = threadIdx.x;
    for (int i = tid; i < WN * WN; i += blockDim.x) rw[i] = root_w[i];
    if (tid < WN) cb[tid] = conv_b[tid];
    __syncthreads();

    int warp = tid >> 5, lane = tid & 31;
    int n = blockIdx.x * 8 + warp;
    if (n >= N) return;
    float hv = g_h[(size_t)n * WN + lane];
    float denom = fmaxf(g_deg[n], 1.f);
    float acc = g_aggr[(size_t)n * WN + lane] / denom + cb[lane];
#pragma unroll
    for (int i = 0; i < WN; i++) {
        float hi = __shfl_sync(0xffffffffu, hv, i);
        acc = fmaf(hi, rw[i * WN + lane], acc);
    }
    if (doRelu) acc = fmaxf(acc, 0.f);
    g_h[(size_t)n * WN + lane] = acc;
}

// out = relu(h @ fc2_w + fc2_b) @ fc3_w + fc3_b   (one 128-thread block/node)
__global__ __launch_bounds__(128)
void head_kernel(const float* __restrict__ fc2_w, const float* __restrict__ fc2_b,
                 const float* __restrict__ fc3_w, const float* __restrict__ fc3_b,
                 float* __restrict__ out)
{
    int n = blockIdx.x, tid = threadIdx.x;
    __shared__ float sh[WN];
    __shared__ float red[4];
    if (tid < WN) sh[tid] = g_h[(size_t)n * WN + tid];
    __syncthreads();
    float a = fc2_b[tid];
#pragma unroll
    for (int i = 0; i < WN; i++) a = fmaf(sh[i], fc2_w[i * 128 + tid], a);
    a = fmaxf(a, 0.f) * fc3_w[tid];
#pragma unroll
    for (int o = 16; o; o >>= 1) a += __shfl_xor_sync(0xffffffffu, a, o);
    if ((tid & 31) == 0) red[tid >> 5] = a;
    __syncthreads();
    if (tid == 0) out[n] = red[0] + red[1] + red[2] + red[3] + fc3_b[0];
}

// ---------------- launch ----------------------------------------------------
extern "C" void kernel_launch(void* const* d_in, const int* in_sizes, int n_in,
                              void* d_out, int out_size)
{
    const float* x      = (const float*)d_in[0];
    const int*   ei     = (const int*)  d_in[1];
    const float* ea     = (const float*)d_in[2];
    const float* fc1_w  = (const float*)d_in[3];
    const float* fc1_b  = (const float*)d_in[4];
    const float* k1_w   = (const float*)d_in[5];
    const float* k1_b   = (const float*)d_in[6];
    const float* k2_w   = (const float*)d_in[7];
    const float* k2_b   = (const float*)d_in[8];
    const float* k3_w   = (const float*)d_in[9];
    const float* k3_b   = (const float*)d_in[10];
    const float* root_w = (const float*)d_in[11];
    const float* conv_b = (const float*)d_in[12];
    const float* fc2_w  = (const float*)d_in[13];
    const float* fc2_b  = (const float*)d_in[14];
    const float* fc3_w  = (const float*)d_in[15];
    const float* fc3_b  = (const float*)d_in[16];
    float* out = (float*)d_out;

    const int N = in_sizes[0] / IN_W;
    const int E = in_sizes[1] / 2;
    const int* src = ei;
    const int* dst = ei + E;

    float *aggr, *deg;
    __half *we;
    __nv_bfloat16 *h1h, *h1l, *h2h, *h2l, *k2h, *k2l, *k3h, *k3l;
    cudaGetSymbolAddress((void**)&we,   g_we);
    cudaGetSymbolAddress((void**)&aggr, g_aggr);
    cudaGetSymbolAddress((void**)&deg,  g_deg);
    cudaGetSymbolAddress((void**)&h1h,  g_h1h);
    cudaGetSymbolAddress((void**)&h1l,  g_h1l);
    cudaGetSymbolAddress((void**)&h2h,  g_h2h);
    cudaGetSymbolAddress((void**)&h2l,  g_h2l);
    cudaGetSymbolAddress((void**)&k2h,  g_k2h);
    cudaGetSymbolAddress((void**)&k2l,  g_k2l);
    cudaGetSymbolAddress((void**)&k3h,  g_k3h);
    cudaGetSymbolAddress((void**)&k3l,  g_k3l);

    static bool attr_done = false;
    if (!attr_done) {
        cudaFuncSetAttribute(mma_split_gemm, cudaFuncAttributeMaxDynamicSharedMemorySize, SMEM_BYTES);
        attr_done = true;
    }

    // --- launch order: GEMM3 at launch index 5 for the ncu -s 5 -c 1 window ---
    edge_fc1_kernel<<<(E + 1) / 2, 256>>>(ea, k1_w, k1_b, E);                            // 0
    split_kernel<<<((WK / 2) * WK + 255) / 256, 256>>>(k2_w, k2h, k2l, (WK / 2) * WK);   // 1
    split_kernel<<<(WK * WN * WN + 255) / 256, 256>>>(k3_w, k3h, k3l, WK * WN * WN);     // 2

    // GEMM2: h2 = relu(h1 @ k2_w + k2_b), split bf16 out.  M=E, N=256, K=128
    {
        dim3 grid(WK / 128, (E + 127) / 128);
        mma_split_gemm<<<grid, 256, SMEM_BYTES>>>(h1h, h1l, k2h, k2l, k2_b,              // 3
                                                  nullptr, h2h, h2l, nullptr, E, WK, WK / 2, 1, 1);
    }
    fc1_kernel<<<(N + 7) / 8, 256>>>(x, fc1_w, fc1_b, N);                                // 4
    // GEMM3: w_e = h2 @ k3_w + k3_b, fp16 out.  M=E, N=1024, K=256
    {
        dim3 grid(WN * WN / 128, (E + 127) / 128);
        mma_split_gemm<<<grid, 256, SMEM_BYTES>>>(h2h, h2l, k3h, k3l, k3_b,              // 5
                                                  nullptr, nullptr, nullptr, we, E, WN * WN, WK, 0, 2);
    }

    // in-degree
    cudaMemsetAsync(deg, 0, (size_t)N * sizeof(float));
    deg_kernel<<<(E + 255) / 256, 256>>>(dst, E);

    // message passing
    for (int d = 0; d < DEPTH; d++) {
        cudaMemsetAsync(aggr, 0, (size_t)N * WN * sizeof(float));
        msg_scatter_kernel<<<(E + 7) / 8, 256>>>(src, dst, E);
        combine_kernel<<<(N + 7) / 8, 256>>>(root_w, conv_b, N, d != DEPTH - 1 ? 1 : 0);
    }

    // head
    head_kernel<<<N, 128>>>(fc2_w, fc2_b, fc3_w, fc3_b, out);
}

// round 6
// speedup vs baseline: 1.7992x; 1.1771x over previous
#include <cuda_runtime.h>
#include <cuda_bf16.h>
#include <cuda_fp16.h>
#include <cstdint>

// Problem constants (fixed by the dataset)
#define NN_NODES 10000
#define NN_EDGES 120000
#define IN_W 6
#define WN 32
#define WK 256
#define DEPTH 4

// ---------------- scratch (device globals; no allocation allowed) ----------
__device__ __half        g_we [(size_t)NN_EDGES * WN * WN];   // per-edge weight mats (fp16)
__device__ __nv_bfloat16 g_h1h[(size_t)NN_EDGES * (WK / 2)];
__device__ __nv_bfloat16 g_h1l[(size_t)NN_EDGES * (WK / 2)];
__device__ __nv_bfloat16 g_h2h[(size_t)NN_EDGES * WK];
__device__ __nv_bfloat16 g_h2l[(size_t)NN_EDGES * WK];
__device__ __nv_bfloat16 g_k2h[(WK / 2) * WK];
__device__ __nv_bfloat16 g_k2l[(WK / 2) * WK];
__device__ __nv_bfloat16 g_k3h[WK * WN * WN];
__device__ __nv_bfloat16 g_k3l[WK * WN * WN];
__device__ float g_h   [(size_t)NN_NODES * WN];
__device__ float g_aggr[(size_t)NN_NODES * WN];
__device__ float g_deg [NN_NODES];

// ============================================================================
// bf16-split tensor-core GEMM: C = act(A@B + bias)
// A [M,K] row-major as (Ah,Al) bf16; B [K,N] row-major as (Bh,Bl) bf16.
// C ≈ Ah*Bh + Al*Bh + Ah*Bl  (fp32 accum).
// Block tile 128x128, BK=32, 256 threads (8 warps, 2x4), warp tile 64x32.
// R6 change: B-frags resident / per-mt A-frags inner loop (live regs ~110)
//            + __launch_bounds__(256,2) for 2 CTAs/SM.
// ============================================================================

#define SA_PAD 40
#define SB_PAD 136
#define AH_OFF 0
#define AL_OFF (128 * SA_PAD)
#define BH_OFF (2 * 128 * SA_PAD)
#define BL_OFF (BH_OFF + 32 * SB_PAD)
#define BUF_H  (BL_OFF + 32 * SB_PAD)
#define SMEM_BYTES (2 * BUF_H * 2)          // 75776 bytes

__device__ __forceinline__ void cp16(uint32_t dst, const void* src, int sbytes) {
    asm volatile("cp.async.cg.shared.global [%0], [%1], 16, %2;\n"
                 :: "r"(dst), "l"(src), "r"(sbytes));
}
__device__ __forceinline__ void ldsm_x4(uint32_t* r, uint32_t addr) {
    asm volatile("ldmatrix.sync.aligned.m8n8.x4.shared.b16 {%0,%1,%2,%3}, [%4];"
                 : "=r"(r[0]), "=r"(r[1]), "=r"(r[2]), "=r"(r[3]) : "r"(addr));
}
__device__ __forceinline__ void ldsm_x2t(uint32_t& b0, uint32_t& b1, uint32_t addr) {
    asm volatile("ldmatrix.sync.aligned.m8n8.x2.trans.shared.b16 {%0,%1}, [%2];"
                 : "=r"(b0), "=r"(b1) : "r"(addr));
}
__device__ __forceinline__ void mma16816(float* c, const uint32_t* a, uint32_t b0, uint32_t b1) {
    asm volatile("mma.sync.aligned.m16n8k16.row.col.f32.bf16.bf16.f32 "
                 "{%0,%1,%2,%3}, {%4,%5,%6,%7}, {%8,%9}, {%0,%1,%2,%3};"
                 : "+f"(c[0]), "+f"(c[1]), "+f"(c[2]), "+f"(c[3])
                 : "r"(a[0]), "r"(a[1]), "r"(a[2]), "r"(a[3]), "r"(b0), "r"(b1));
}

__global__ __launch_bounds__(256, 2)
void mma_split_gemm(const __nv_bfloat16* __restrict__ Ah, const __nv_bfloat16* __restrict__ Al,
                    const __nv_bfloat16* __restrict__ Bh, const __nv_bfloat16* __restrict__ Bl,
                    const float* __restrict__ bias,
                    float* __restrict__ Cf, __nv_bfloat16* __restrict__ Ch, __nv_bfloat16* __restrict__ Cl,
                    __half* __restrict__ Cp,
                    int M, int N, int K, int doRelu, int outMode)
{
    extern __shared__ __nv_bfloat16 smem[];
    const int tid  = threadIdx.x;
    const int lane = tid & 31;
    const int wid  = tid >> 5;
    const int bm = blockIdx.y * 128;
    const int bn = blockIdx.x * 128;
    const int warp_m = (wid & 1) * 64;
    const int warp_n = (wid >> 1) * 32;

    uint32_t su = (uint32_t)__cvta_generic_to_shared(smem);

    float C[4][4][4];
#pragma unroll
    for (int mt = 0; mt < 4; mt++)
#pragma unroll
        for (int nt = 0; nt < 4; nt++)
#pragma unroll
            for (int q = 0; q < 4; q++) C[mt][nt][q] = 0.f;

    const int nk = K / 32;

    auto load_tile = [&](int kt, int buf) {
        const int k0 = kt * 32;
        const uint32_t sbase = su + (uint32_t)buf * BUF_H * 2;
#pragma unroll
        for (int t = 0; t < 4; t++) {
            int cid = tid + t * 256;
            int mat = cid >> 9;
            int rr  = (cid & 511) >> 2;
            int c8  = (cid & 3) * 8;
            int gr  = bm + rr;
            int ok  = (gr < M) ? 16 : 0;
            const __nv_bfloat16* src = (mat ? Al : Ah) + (size_t)(ok ? gr : 0) * K + k0 + c8;
            uint32_t dst = sbase + (uint32_t)((mat ? AL_OFF : AH_OFF) + rr * SA_PAD + c8) * 2;
            cp16(dst, src, ok);
        }
#pragma unroll
        for (int t = 0; t < 4; t++) {
            int cid = tid + t * 256;
            int mat = cid >> 9;
            int rr  = (cid & 511) >> 4;
            int c8  = (cid & 15) * 8;
            const __nv_bfloat16* src = (mat ? Bl : Bh) + (size_t)(k0 + rr) * N + bn + c8;
            uint32_t dst = sbase + (uint32_t)((mat ? BL_OFF : BH_OFF) + rr * SB_PAD + c8) * 2;
            cp16(dst, src, 16);
        }
    };

    load_tile(0, 0);
    asm volatile("cp.async.commit_group;\n" ::: "memory");

    for (int i = 0; i < nk; i++) {
        const int buf = i & 1;
        if (i + 1 < nk) {
            load_tile(i + 1, buf ^ 1);
            asm volatile("cp.async.commit_group;\n" ::: "memory");
            asm volatile("cp.async.wait_group 1;\n" ::: "memory");
        } else {
            asm volatile("cp.async.wait_group 0;\n" ::: "memory");
        }
        __syncthreads();

        const uint32_t aH = su + (uint32_t)(buf * BUF_H + AH_OFF) * 2;
        const uint32_t aL = su + (uint32_t)(buf * BUF_H + AL_OFF) * 2;
        const uint32_t bH = su + (uint32_t)(buf * BUF_H + BH_OFF) * 2;
        const uint32_t bL = su + (uint32_t)(buf * BUF_H + BL_OFF) * 2;

        const int arow = lane & 15;
        const int acol = (lane >> 4) * 8;
        const int brow = lane & 15;

#pragma unroll
        for (int ks = 0; ks < 32; ks += 16) {
            // B fragments resident: 4 nt x (hi 2 + lo 2) = 16 regs
            uint32_t bh[4][2], bl[4][2];
#pragma unroll
            for (int nt = 0; nt < 4; nt++) {
                uint32_t boff = (uint32_t)((ks + brow) * SB_PAD + warp_n + nt * 8) * 2;
                ldsm_x2t(bh[nt][0], bh[nt][1], bH + boff);
                ldsm_x2t(bl[nt][0], bl[nt][1], bL + boff);
            }
            // Per-mt A fragments: 8 regs live at a time
#pragma unroll
            for (int mt = 0; mt < 4; mt++) {
                uint32_t ah[4], al[4];
                uint32_t off = (uint32_t)((warp_m + mt * 16 + arow) * SA_PAD + ks + acol) * 2;
                ldsm_x4(ah, aH + off);
                ldsm_x4(al, aL + off);
#pragma unroll
                for (int nt = 0; nt < 4; nt++) {
                    mma16816(C[mt][nt], ah, bh[nt][0], bh[nt][1]);
                    mma16816(C[mt][nt], al, bh[nt][0], bh[nt][1]);
                    mma16816(C[mt][nt], ah, bl[nt][0], bl[nt][1]);
                }
            }
        }
        __syncthreads();
    }

#pragma unroll
    for (int mt = 0; mt < 4; mt++) {
#pragma unroll
        for (int nt = 0; nt < 4; nt++) {
            int r0  = bm + warp_m + mt * 16 + (lane >> 2);
            int col = bn + warp_n + nt * 8 + (lane & 3) * 2;
            float b0 = bias[col], b1 = bias[col + 1];
            float v0 = C[mt][nt][0] + b0;
            float v1 = C[mt][nt][1] + b1;
            float v2 = C[mt][nt][2] + b0;
            float v3 = C[mt][nt][3] + b1;
            if (doRelu) {
                v0 = fmaxf(v0, 0.f); v1 = fmaxf(v1, 0.f);
                v2 = fmaxf(v2, 0.f); v3 = fmaxf(v3, 0.f);
            }
            if (outMode == 1) {
                if (r0 < M) {
                    __nv_bfloat16 h0 = __float2bfloat16(v0), h1 = __float2bfloat16(v1);
                    __nv_bfloat162 hp; hp.x = h0; hp.y = h1;
                    __nv_bfloat162 lp; lp.x = __float2bfloat16(v0 - __bfloat162float(h0));
                    lp.y = __float2bfloat16(v1 - __bfloat162float(h1));
                    *reinterpret_cast<__nv_bfloat162*>(&Ch[(size_t)r0 * N + col]) = hp;
                    *reinterpret_cast<__nv_bfloat162*>(&Cl[(size_t)r0 * N + col]) = lp;
                }
                if (r0 + 8 < M) {
                    __nv_bfloat16 h2 = __float2bfloat16(v2), h3 = __float2bfloat16(v3);
                    __nv_bfloat162 hp; hp.x = h2; hp.y = h3;
                    __nv_bfloat162 lp; lp.x = __float2bfloat16(v2 - __bfloat162float(h2));
                    lp.y = __float2bfloat16(v3 - __bfloat162float(h3));
                    *reinterpret_cast<__nv_bfloat162*>(&Ch[(size_t)(r0 + 8) * N + col]) = hp;
                    *reinterpret_cast<__nv_bfloat162*>(&Cl[(size_t)(r0 + 8) * N + col]) = lp;
                }
            } else if (outMode == 2) {
                if (r0 < M) {
                    __half2 p; p.x = __float2half(v0); p.y = __float2half(v1);
                    *reinterpret_cast<__half2*>(&Cp[(size_t)r0 * N + col]) = p;
                }
                if (r0 + 8 < M) {
                    __half2 p; p.x = __float2half(v2); p.y = __float2half(v3);
                    *reinterpret_cast<__half2*>(&Cp[(size_t)(r0 + 8) * N + col]) = p;
                }
            } else {
                if (r0 < M) {
                    float2 p; p.x = v0; p.y = v1;
                    *reinterpret_cast<float2*>(&Cf[(size_t)r0 * N + col]) = p;
                }
                if (r0 + 8 < M) {
                    float2 p; p.x = v2; p.y = v3;
                    *reinterpret_cast<float2*>(&Cf[(size_t)(r0 + 8) * N + col]) = p;
                }
            }
        }
    }
}

// ---------------- small kernels --------------------------------------------

__global__ void split_kernel(const float* __restrict__ in, __nv_bfloat16* __restrict__ hi,
                             __nv_bfloat16* __restrict__ lo, int n)
{
    int i = blockIdx.x * blockDim.x + threadIdx.x;
    if (i < n) {
        float v = in[i];
        __nv_bfloat16 h = __float2bfloat16(v);
        hi[i] = h;
        lo[i] = __float2bfloat16(v - __bfloat162float(h));
    }
}

// h1 = relu(ea @ k1_w + k1_b), written split. 256 threads = 2 edges per block.
__global__ __launch_bounds__(256)
void edge_fc1_kernel(const float* __restrict__ ea, const float* __restrict__ w,
                     const float* __restrict__ b, int E)
{
    int sub = threadIdx.x >> 7;
    int tid = threadIdx.x & 127;
    int e = blockIdx.x * 2 + sub;
    if (e >= E) return;
    __shared__ float a[2][IN_W];
    if (tid < IN_W) a[sub][tid] = ea[(size_t)e * IN_W + tid];
    __syncthreads();
    float acc = b[tid];
#pragma unroll
    for (int i = 0; i < IN_W; i++) acc = fmaf(a[sub][i], w[i * (WK / 2) + tid], acc);
    acc = fmaxf(acc, 0.f);
    __nv_bfloat16 h = __float2bfloat16(acc);
    g_h1h[(size_t)e * (WK / 2) + tid] = h;
    g_h1l[(size_t)e * (WK / 2) + tid] = __float2bfloat16(acc - __bfloat162float(h));
}

__global__ void deg_kernel(const int* __restrict__ dst, int E)
{
    int e = blockIdx.x * blockDim.x + threadIdx.x;
    if (e < E) atomicAdd(&g_deg[dst[e]], 1.f);
}

__global__ __launch_bounds__(256)
void fc1_kernel(const float* __restrict__ x, const float* __restrict__ w,
                const float* __restrict__ b, int N)
{
    int warp = threadIdx.x >> 5, lane = threadIdx.x & 31;
    int n = blockIdx.x * 8 + warp;
    if (n >= N) return;
    float xv = (lane < IN_W) ? x[(size_t)n * IN_W + lane] : 0.f;
    float acc = b[lane];
#pragma unroll
    for (int i = 0; i < IN_W; i++) {
        float xi = __shfl_sync(0xffffffffu, xv, i);
        acc = fmaf(xi, w[i * WN + lane], acc);
    }
    g_h[(size_t)n * WN + lane] = acc;
}

// per-edge matvec msg = h[src] @ w_e (fp16), scattered to aggr[dst].
__global__ __launch_bounds__(256)
void msg_scatter_kernel(const int* __restrict__ src, const int* __restrict__ dst, int E)
{
    int warp = threadIdx.x >> 5, lane = threadIdx.x & 31;
    int e = blockIdx.x * 8 + warp;
    if (e >= E) return;
    int s = src[e], d = dst[e];
    int j = lane & 15;
    int r = lane >> 4;
    float hv = g_h[(size_t)s * WN + lane];
    const __half2* w2 = reinterpret_cast<const __half2*>(&g_we[(size_t)e * WN * WN]);
    float ax = 0.f, ay = 0.f;
#pragma unroll
    for (int i = 0; i < WN; i += 2) {
        float hi = __shfl_sync(0xffffffffu, hv, i + r);
        float2 wf = __half22float2(w2[(i + r) * 16 + j]);
        ax = fmaf(hi, wf.x, ax);
        ay = fmaf(hi, wf.y, ay);
    }
    ax += __shfl_xor_sync(0xffffffffu, ax, 16);
    ay += __shfl_xor_sync(0xffffffffu, ay, 16);
    if (lane < 16) {
        atomicAdd(&g_aggr[(size_t)d * WN + 2 * j],     ax);
        atomicAdd(&g_aggr[(size_t)d * WN + 2 * j + 1], ay);
    }
}

__global__ __launch_bounds__(256)
void combine_kernel(const float* __restrict__ root_w, const float* __restrict__ conv_b,
                    int N, int doRelu)
{
    __shared__ float rw[WN * WN];
    __shared__ float cb[WN];
    int tid = threadIdx.x;
    for (int i = tid; i < WN * WN; i += blockDim.x) rw[i] = root_w[i];
    if (tid < WN) cb[tid] = conv_b[tid];
    __syncthreads();

    int warp = tid >> 5, lane = tid & 31;
    int n = blockIdx.x * 8 + warp;
    if (n >= N) return;
    float hv = g_h[(size_t)n * WN + lane];
    float denom = fmaxf(g_deg[n], 1.f);
    float acc = g_aggr[(size_t)n * WN + lane] / denom + cb[lane];
#pragma unroll
    for (int i = 0; i < WN; i++) {
        float hi = __shfl_sync(0xffffffffu, hv, i);
        acc = fmaf(hi, rw[i * WN + lane], acc);
    }
    if (doRelu) acc = fmaxf(acc, 0.f);
    g_h[(size_t)n * WN + lane] = acc;
}

__global__ __launch_bounds__(128)
void head_kernel(const float* __restrict__ fc2_w, const float* __restrict__ fc2_b,
                 const float* __restrict__ fc3_w, const float* __restrict__ fc3_b,
                 float* __restrict__ out)
{
    int n = blockIdx.x, tid = threadIdx.x;
    __shared__ float sh[WN];
    __shared__ float red[4];
    if (tid < WN) sh[tid] = g_h[(size_t)n * WN + tid];
    __syncthreads();
    float a = fc2_b[tid];
#pragma unroll
    for (int i = 0; i < WN; i++) a = fmaf(sh[i], fc2_w[i * 128 + tid], a);
    a = fmaxf(a, 0.f) * fc3_w[tid];
#pragma unroll
    for (int o = 16; o; o >>= 1) a += __shfl_xor_sync(0xffffffffu, a, o);
    if ((tid & 31) == 0) red[tid >> 5] = a;
    __syncthreads();
    if (tid == 0) out[n] = red[0] + red[1] + red[2] + red[3] + fc3_b[0];
}

// ---------------- launch ----------------------------------------------------
extern "C" void kernel_launch(void* const* d_in, const int* in_sizes, int n_in,
                              void* d_out, int out_size)
{
    const float* x      = (const float*)d_in[0];
    const int*   ei     = (const int*)  d_in[1];
    const float* ea     = (const float*)d_in[2];
    const float* fc1_w  = (const float*)d_in[3];
    const float* fc1_b  = (const float*)d_in[4];
    const float* k1_w   = (const float*)d_in[5];
    const float* k1_b   = (const float*)d_in[6];
    const float* k2_w   = (const float*)d_in[7];
    const float* k2_b   = (const float*)d_in[8];
    const float* k3_w   = (const float*)d_in[9];
    const float* k3_b   = (const float*)d_in[10];
    const float* root_w = (const float*)d_in[11];
    const float* conv_b = (const float*)d_in[12];
    const float* fc2_w  = (const float*)d_in[13];
    const float* fc2_b  = (const float*)d_in[14];
    const float* fc3_w  = (const float*)d_in[15];
    const float* fc3_b  = (const float*)d_in[16];
    float* out = (float*)d_out;

    const int N = in_sizes[0] / IN_W;
    const int E = in_sizes[1] / 2;
    const int* src = ei;
    const int* dst = ei + E;

    float *aggr, *deg;
    __half *we;
    __nv_bfloat16 *h1h, *h1l, *h2h, *h2l, *k2h, *k2l, *k3h, *k3l;
    cudaGetSymbolAddress((void**)&we,   g_we);
    cudaGetSymbolAddress((void**)&aggr, g_aggr);
    cudaGetSymbolAddress((void**)&deg,  g_deg);
    cudaGetSymbolAddress((void**)&h1h,  g_h1h);
    cudaGetSymbolAddress((void**)&h1l,  g_h1l);
    cudaGetSymbolAddress((void**)&h2h,  g_h2h);
    cudaGetSymbolAddress((void**)&h2l,  g_h2l);
    cudaGetSymbolAddress((void**)&k2h,  g_k2h);
    cudaGetSymbolAddress((void**)&k2l,  g_k2l);
    cudaGetSymbolAddress((void**)&k3h,  g_k3h);
    cudaGetSymbolAddress((void**)&k3l,  g_k3l);

    static bool attr_done = false;
    if (!attr_done) {
        cudaFuncSetAttribute(mma_split_gemm, cudaFuncAttributeMaxDynamicSharedMemorySize, SMEM_BYTES);
        attr_done = true;
    }

    // launch order: GEMM3 at index 5 for the ncu -s 5 -c 1 window
    edge_fc1_kernel<<<(E + 1) / 2, 256>>>(ea, k1_w, k1_b, E);                            // 0
    split_kernel<<<((WK / 2) * WK + 255) / 256, 256>>>(k2_w, k2h, k2l, (WK / 2) * WK);   // 1
    split_kernel<<<(WK * WN * WN + 255) / 256, 256>>>(k3_w, k3h, k3l, WK * WN * WN);     // 2

    // GEMM2: h2 = relu(h1 @ k2_w + k2_b), split bf16 out.  M=E, N=256, K=128
    {
        dim3 grid(WK / 128, (E + 127) / 128);
        mma_split_gemm<<<grid, 256, SMEM_BYTES>>>(h1h, h1l, k2h, k2l, k2_b,              // 3
                                                  nullptr, h2h, h2l, nullptr, E, WK, WK / 2, 1, 1);
    }
    fc1_kernel<<<(N + 7) / 8, 256>>>(x, fc1_w, fc1_b, N);                                // 4
    // GEMM3: w_e = h2 @ k3_w + k3_b, fp16 out.  M=E, N=1024, K=256
    {
        dim3 grid(WN * WN / 128, (E + 127) / 128);
        mma_split_gemm<<<grid, 256, SMEM_BYTES>>>(h2h, h2l, k3h, k3l, k3_b,              // 5
                                                  nullptr, nullptr, nullptr, we, E, WN * WN, WK, 0, 2);
    }

    // in-degree
    cudaMemsetAsync(deg, 0, (size_t)N * sizeof(float));
    deg_kernel<<<(E + 255) / 256, 256>>>(dst, E);

    // message passing
    for (int d = 0; d < DEPTH; d++) {
        cudaMemsetAsync(aggr, 0, (size_t)N * WN * sizeof(float));
        msg_scatter_kernel<<<(E + 7) / 8, 256>>>(src, dst, E);
        combine_kernel<<<(N + 7) / 8, 256>>>(root_w, conv_b, N, d != DEPTH - 1 ? 1 : 0);
    }

    // head
    head_kernel<<<N, 128>>>(fc2_w, fc2_b, fc3_w, fc3_b, out);
}

// round 7
// speedup vs baseline: 2.1409x; 1.1899x over previous
#include <cuda_runtime.h>
#include <cuda_bf16.h>
#include <cuda_fp16.h>
#include <cstdint>

// Problem constants (fixed by the dataset)
#define NN_NODES 10000
#define NN_EDGES 120000
#define IN_W 6
#define WN 32
#define WK 256
#define DEPTH 4

// ---------------- scratch (device globals; no allocation allowed) ----------
__device__ __half g_we [(size_t)NN_EDGES * WN * WN];   // per-edge weight mats (fp16)
__device__ __half g_h1h[(size_t)NN_EDGES * (WK / 2)];  // edge MLP hidden 1 (fp16 hi)
__device__ __half g_h1l[(size_t)NN_EDGES * (WK / 2)];  // edge MLP hidden 1 (fp16 lo)
__device__ __half g_h2h[(size_t)NN_EDGES * WK];        // edge MLP hidden 2 (fp16 hi)
__device__ __half g_h2l[(size_t)NN_EDGES * WK];        // edge MLP hidden 2 (fp16 lo)
__device__ __half g_k2h[(WK / 2) * WK];
__device__ __half g_k2l[(WK / 2) * WK];
__device__ __half g_k3 [WK * WN * WN];                 // k3 single fp16 (2-term GEMM3)
__device__ float g_h   [(size_t)NN_NODES * WN];
__device__ float g_aggr[(size_t)NN_NODES * WN];
__device__ float g_deg [NN_NODES];

// ============================================================================
// fp16-split tensor-core GEMM: C = act(A@B + bias)
// A [M,K] row-major as (Ah,Al) fp16; B [K,N] row-major fp16 (Bh [+ Bl]).
// USE_BL=1: C ≈ Ah*Bh + Al*Bh + Ah*Bl  (3-term, ~2^-22 operand err)
// USE_BL=0: C ≈ Ah*Bh + Al*Bh          (2-term, ~2.8e-4 from B rounding)
// Block tile 128x128, BK=32, 256 threads (8 warps, 2x4), warp tile 64x32.
// ============================================================================

#define SA_PAD 40
#define SB_PAD 136
#define AH_OFF 0
#define AL_OFF (128 * SA_PAD)
#define BH_OFF (2 * 128 * SA_PAD)
#define BL_OFF (BH_OFF + 32 * SB_PAD)
#define BUF_H  (BL_OFF + 32 * SB_PAD)
#define SMEM_BYTES (2 * BUF_H * 2)          // 75776 bytes

__device__ __forceinline__ void cp16(uint32_t dst, const void* src, int sbytes) {
    asm volatile("cp.async.cg.shared.global [%0], [%1], 16, %2;\n"
                 :: "r"(dst), "l"(src), "r"(sbytes));
}
__device__ __forceinline__ void ldsm_x4(uint32_t* r, uint32_t addr) {
    asm volatile("ldmatrix.sync.aligned.m8n8.x4.shared.b16 {%0,%1,%2,%3}, [%4];"
                 : "=r"(r[0]), "=r"(r[1]), "=r"(r[2]), "=r"(r[3]) : "r"(addr));
}
__device__ __forceinline__ void ldsm_x4t(uint32_t* r, uint32_t addr) {
    asm volatile("ldmatrix.sync.aligned.m8n8.x4.trans.shared.b16 {%0,%1,%2,%3}, [%4];"
                 : "=r"(r[0]), "=r"(r[1]), "=r"(r[2]), "=r"(r[3]) : "r"(addr));
}
__device__ __forceinline__ void mma16816(float* c, const uint32_t* a, uint32_t b0, uint32_t b1) {
    asm volatile("mma.sync.aligned.m16n8k16.row.col.f32.f16.f16.f32 "
                 "{%0,%1,%2,%3}, {%4,%5,%6,%7}, {%8,%9}, {%0,%1,%2,%3};"
                 : "+f"(c[0]), "+f"(c[1]), "+f"(c[2]), "+f"(c[3])
                 : "r"(a[0]), "r"(a[1]), "r"(a[2]), "r"(a[3]), "r"(b0), "r"(b1));
}

template<int USE_BL>
__global__ __launch_bounds__(256, 2)
void mma_split_gemm(const __half* __restrict__ Ah, const __half* __restrict__ Al,
                    const __half* __restrict__ Bh, const __half* __restrict__ Bl,
                    const float* __restrict__ bias,
                    __half* __restrict__ Ch, __half* __restrict__ Cl, __half* __restrict__ Cp,
                    int M, int N, int K, int doRelu, int outMode)
{
    extern __shared__ __half smem[];
    const int tid  = threadIdx.x;
    const int lane = tid & 31;
    const int wid  = tid >> 5;
    const int bm = blockIdx.y * 128;
    const int bn = blockIdx.x * 128;
    const int warp_m = (wid & 1) * 64;
    const int warp_n = (wid >> 1) * 32;

    uint32_t su = (uint32_t)__cvta_generic_to_shared(smem);

    float C[4][4][4];
#pragma unroll
    for (int mt = 0; mt < 4; mt++)
#pragma unroll
        for (int nt = 0; nt < 4; nt++)
#pragma unroll
            for (int q = 0; q < 4; q++) C[mt][nt][q] = 0.f;

    const int nk = K / 32;

    auto load_tile = [&](int kt, int buf) {
        const int k0 = kt * 32;
        const uint32_t sbase = su + (uint32_t)buf * BUF_H * 2;
        // A: hi + lo planes, 512 chunks each (128 rows x 4 16B-chunks)
#pragma unroll
        for (int t = 0; t < 4; t++) {
            int cid = tid + t * 256;
            int mat = cid >> 9;
            int rr  = (cid & 511) >> 2;
            int c8  = (cid & 3) * 8;
            int gr  = bm + rr;
            int ok  = (gr < M) ? 16 : 0;
            const __half* src = (mat ? Al : Ah) + (size_t)(ok ? gr : 0) * K + k0 + c8;
            uint32_t dst = sbase + (uint32_t)((mat ? AL_OFF : AH_OFF) + rr * SA_PAD + c8) * 2;
            cp16(dst, src, ok);
        }
        // B hi: 512 chunks (32 rows x 16 chunks)
#pragma unroll
        for (int t = 0; t < 2; t++) {
            int cid = tid + t * 256;
            int rr  = cid >> 4;
            int c8  = (cid & 15) * 8;
            const __half* src = Bh + (size_t)(k0 + rr) * N + bn + c8;
            uint32_t dst = sbase + (uint32_t)(BH_OFF + rr * SB_PAD + c8) * 2;
            cp16(dst, src, 16);
        }
        if (USE_BL) {
#pragma unroll
            for (int t = 0; t < 2; t++) {
                int cid = tid + t * 256;
                int rr  = cid >> 4;
                int c8  = (cid & 15) * 8;
                const __half* src = Bl + (size_t)(k0 + rr) * N + bn + c8;
                uint32_t dst = sbase + (uint32_t)(BL_OFF + rr * SB_PAD + c8) * 2;
                cp16(dst, src, 16);
            }
        }
    };

    load_tile(0, 0);
    asm volatile("cp.async.commit_group;\n" ::: "memory");

    for (int i = 0; i < nk; i++) {
        const int buf = i & 1;
        if (i + 1 < nk) {
            load_tile(i + 1, buf ^ 1);
            asm volatile("cp.async.commit_group;\n" ::: "memory");
            asm volatile("cp.async.wait_group 1;\n" ::: "memory");
        } else {
            asm volatile("cp.async.wait_group 0;\n" ::: "memory");
        }
        __syncthreads();

        const uint32_t aH = su + (uint32_t)(buf * BUF_H + AH_OFF) * 2;
        const uint32_t aL = su + (uint32_t)(buf * BUF_H + AL_OFF) * 2;
        const uint32_t bH = su + (uint32_t)(buf * BUF_H + BH_OFF) * 2;
        const uint32_t bL = su + (uint32_t)(buf * BUF_H + BL_OFF) * 2;

        const int arow = lane & 15;
        const int acol = (lane >> 4) * 8;
        // x4.trans B lane map: group g=lane>>3; k_off=(g&1)*8+(lane&7); n_off=(g>>1)*8
        const int bk = ((lane >> 3) & 1) * 8 + (lane & 7);
        const int bn8 = (lane >> 4) * 8;

#pragma unroll
        for (int ks = 0; ks < 32; ks += 16) {
            // B fragments: 2 x4t per plane cover all 4 nt (16 cols each)
            uint32_t bh[2][4], bl[2][4];
#pragma unroll
            for (int ntp = 0; ntp < 2; ntp++) {
                uint32_t boff = (uint32_t)((ks + bk) * SB_PAD + warp_n + ntp * 16 + bn8) * 2;
                ldsm_x4t(bh[ntp], bH + boff);
                if (USE_BL) ldsm_x4t(bl[ntp], bL + boff);
            }
#pragma unroll
            for (int mt = 0; mt < 4; mt++) {
                uint32_t ah[4], al[4];
                uint32_t off = (uint32_t)((warp_m + mt * 16 + arow) * SA_PAD + ks + acol) * 2;
                ldsm_x4(ah, aH + off);
                ldsm_x4(al, aL + off);
#pragma unroll
                for (int nt = 0; nt < 4; nt++) {
                    uint32_t b0 = bh[nt >> 1][(nt & 1) * 2];
                    uint32_t b1 = bh[nt >> 1][(nt & 1) * 2 + 1];
                    mma16816(C[mt][nt], ah, b0, b1);
                    mma16816(C[mt][nt], al, b0, b1);
                    if (USE_BL) {
                        uint32_t c0 = bl[nt >> 1][(nt & 1) * 2];
                        uint32_t c1 = bl[nt >> 1][(nt & 1) * 2 + 1];
                        mma16816(C[mt][nt], ah, c0, c1);
                    }
                }
            }
        }
        __syncthreads();
    }

#pragma unroll
    for (int mt = 0; mt < 4; mt++) {
#pragma unroll
        for (int nt = 0; nt < 4; nt++) {
            int r0  = bm + warp_m + mt * 16 + (lane >> 2);
            int col = bn + warp_n + nt * 8 + (lane & 3) * 2;
            float b0 = bias[col], b1 = bias[col + 1];
            float v0 = C[mt][nt][0] + b0;
            float v1 = C[mt][nt][1] + b1;
            float v2 = C[mt][nt][2] + b0;
            float v3 = C[mt][nt][3] + b1;
            if (doRelu) {
                v0 = fmaxf(v0, 0.f); v1 = fmaxf(v1, 0.f);
                v2 = fmaxf(v2, 0.f); v3 = fmaxf(v3, 0.f);
            }
            if (outMode == 1) {
                if (r0 < M) {
                    __half h0 = __float2half(v0), h1 = __float2half(v1);
                    __half2 hp; hp.x = h0; hp.y = h1;
                    __half2 lp; lp.x = __float2half(v0 - __half2float(h0));
                    lp.y = __float2half(v1 - __half2float(h1));
                    *reinterpret_cast<__half2*>(&Ch[(size_t)r0 * N + col]) = hp;
                    *reinterpret_cast<__half2*>(&Cl[(size_t)r0 * N + col]) = lp;
                }
                if (r0 + 8 < M) {
                    __half h2 = __float2half(v2), h3 = __float2half(v3);
                    __half2 hp; hp.x = h2; hp.y = h3;
                    __half2 lp; lp.x = __float2half(v2 - __half2float(h2));
                    lp.y = __float2half(v3 - __half2float(h3));
                    *reinterpret_cast<__half2*>(&Ch[(size_t)(r0 + 8) * N + col]) = hp;
                    *reinterpret_cast<__half2*>(&Cl[(size_t)(r0 + 8) * N + col]) = lp;
                }
            } else {
                if (r0 < M) {
                    __half2 p; p.x = __float2half(v0); p.y = __float2half(v1);
                    *reinterpret_cast<__half2*>(&Cp[(size_t)r0 * N + col]) = p;
                }
                if (r0 + 8 < M) {
                    __half2 p; p.x = __float2half(v2); p.y = __float2half(v3);
                    *reinterpret_cast<__half2*>(&Cp[(size_t)(r0 + 8) * N + col]) = p;
                }
            }
        }
    }
}

// ---------------- small kernels --------------------------------------------

// fp32 -> fp16 hi/lo split
__global__ void split_kernel(const float* __restrict__ in, __half* __restrict__ hi,
                             __half* __restrict__ lo, int n)
{
    int i = blockIdx.x * blockDim.x + threadIdx.x;
    if (i < n) {
        float v = in[i];
        __half h = __float2half(v);
        hi[i] = h;
        lo[i] = __float2half(v - __half2float(h));
    }
}

// fp32 -> fp16 convert
__global__ void convert_kernel(const float* __restrict__ in, __half* __restrict__ o, int n)
{
    int i = blockIdx.x * blockDim.x + threadIdx.x;
    if (i < n) o[i] = __float2half(in[i]);
}

// h1 = relu(ea @ k1_w + k1_b), written split. 256 threads = 2 edges per block.
__global__ __launch_bounds__(256)
void edge_fc1_kernel(const float* __restrict__ ea, const float* __restrict__ w,
                     const float* __restrict__ b, int E)
{
    int sub = threadIdx.x >> 7;
    int tid = threadIdx.x & 127;
    int e = blockIdx.x * 2 + sub;
    if (e >= E) return;
    __shared__ float a[2][IN_W];
    if (tid < IN_W) a[sub][tid] = ea[(size_t)e * IN_W + tid];
    __syncthreads();
    float acc = b[tid];
#pragma unroll
    for (int i = 0; i < IN_W; i++) acc = fmaf(a[sub][i], w[i * (WK / 2) + tid], acc);
    acc = fmaxf(acc, 0.f);
    __half h = __float2half(acc);
    g_h1h[(size_t)e * (WK / 2) + tid] = h;
    g_h1l[(size_t)e * (WK / 2) + tid] = __float2half(acc - __half2float(h));
}

__global__ void deg_kernel(const int* __restrict__ dst, int E)
{
    int e = blockIdx.x * blockDim.x + threadIdx.x;
    if (e < E) atomicAdd(&g_deg[dst[e]], 1.f);
}

__global__ __launch_bounds__(256)
void fc1_kernel(const float* __restrict__ x, const float* __restrict__ w,
                const float* __restrict__ b, int N)
{
    int warp = threadIdx.x >> 5, lane = threadIdx.x & 31;
    int n = blockIdx.x * 8 + warp;
    if (n >= N) return;
    float xv = (lane < IN_W) ? x[(size_t)n * IN_W + lane] : 0.f;
    float acc = b[lane];
#pragma unroll
    for (int i = 0; i < IN_W; i++) {
        float xi = __shfl_sync(0xffffffffu, xv, i);
        acc = fmaf(xi, w[i * WN + lane], acc);
    }
    g_h[(size_t)n * WN + lane] = acc;
}

// per-edge matvec msg = h[src] @ w_e (fp16), scattered to aggr[dst].
__global__ __launch_bounds__(256)
void msg_scatter_kernel(const int* __restrict__ src, const int* __restrict__ dst, int E)
{
    int warp = threadIdx.x >> 5, lane = threadIdx.x & 31;
    int e = blockIdx.x * 8 + warp;
    if (e >= E) return;
    int s = src[e], d = dst[e];
    int j = lane & 15;
    int r = lane >> 4;
    float hv = g_h[(size_t)s * WN + lane];
    const __half2* w2 = reinterpret_cast<const __half2*>(&g_we[(size_t)e * WN * WN]);
    float ax = 0.f, ay = 0.f;
#pragma unroll
    for (int i = 0; i < WN; i += 2) {
        float hi = __shfl_sync(0xffffffffu, hv, i + r);
        float2 wf = __half22float2(w2[(i + r) * 16 + j]);
        ax = fmaf(hi, wf.x, ax);
        ay = fmaf(hi, wf.y, ay);
    }
    ax += __shfl_xor_sync(0xffffffffu, ax, 16);
    ay += __shfl_xor_sync(0xffffffffu, ay, 16);
    if (lane < 16) {
        atomicAdd(&g_aggr[(size_t)d * WN + 2 * j],     ax);
        atomicAdd(&g_aggr[(size_t)d * WN + 2 * j + 1], ay);
    }
}

// h = [relu]( aggr/denom + h @ root_w + conv_b ); also zeroes aggr for next round
__global__ __launch_bounds__(256)
void combine_kernel(const float* __restrict__ root_w, const float* __restrict__ conv_b,
                    int N, int doRelu)
{
    __shared__ float rw[WN * WN];
    __shared__ float cb[WN];
    int tid = threadIdx.x;
    for (int i = tid; i < WN * WN; i += blockDim.x) rw[i] = root_w[i];
    if (tid < WN) cb[tid] = conv_b[tid];
    __syncthreads();

    int warp = tid >> 5, lane = tid & 31;
    int n = blockIdx.x * 8 + warp;
    if (n >= N) return;
    float hv = g_h[(size_t)n * WN + lane];
    float denom = fmaxf(g_deg[n], 1.f);
    float acc = g_aggr[(size_t)n * WN + lane] / denom + cb[lane];
    g_aggr[(size_t)n * WN + lane] = 0.f;   // reset for next depth
#pragma unroll
    for (int i = 0; i < WN; i++) {
        float hi = __shfl_sync(0xffffffffu, hv, i);
        acc = fmaf(hi, rw[i * WN + lane], acc);
    }
    if (doRelu) acc = fmaxf(acc, 0.f);
    g_h[(size_t)n * WN + lane] = acc;
}

__global__ __launch_bounds__(128)
void head_kernel(const float* __restrict__ fc2_w, const float* __restrict__ fc2_b,
                 const float* __restrict__ fc3_w, const float* __restrict__ fc3_b,
                 float* __restrict__ out)
{
    int n = blockIdx.x, tid = threadIdx.x;
    __shared__ float sh[WN];
    __shared__ float red[4];
    if (tid < WN) sh[tid] = g_h[(size_t)n * WN + tid];
    __syncthreads();
    float a = fc2_b[tid];
#pragma unroll
    for (int i = 0; i < WN; i++) a = fmaf(sh[i], fc2_w[i * 128 + tid], a);
    a = fmaxf(a, 0.f) * fc3_w[tid];
#pragma unroll
    for (int o = 16; o; o >>= 1) a += __shfl_xor_sync(0xffffffffu, a, o);
    if ((tid & 31) == 0) red[tid >> 5] = a;
    __syncthreads();
    if (tid == 0) out[n] = red[0] + red[1] + red[2] + red[3] + fc3_b[0];
}

// ---------------- launch ----------------------------------------------------
extern "C" void kernel_launch(void* const* d_in, const int* in_sizes, int n_in,
                              void* d_out, int out_size)
{
    const float* x      = (const float*)d_in[0];
    const int*   ei     = (const int*)  d_in[1];
    const float* ea     = (const float*)d_in[2];
    const float* fc1_w  = (const float*)d_in[3];
    const float* fc1_b  = (const float*)d_in[4];
    const float* k1_w   = (const float*)d_in[5];
    const float* k1_b   = (const float*)d_in[6];
    const float* k2_w   = (const float*)d_in[7];
    const float* k2_b   = (const float*)d_in[8];
    const float* k3_w   = (const float*)d_in[9];
    const float* k3_b   = (const float*)d_in[10];
    const float* root_w = (const float*)d_in[11];
    const float* conv_b = (const float*)d_in[12];
    const float* fc2_w  = (const float*)d_in[13];
    const float* fc2_b  = (const float*)d_in[14];
    const float* fc3_w  = (const float*)d_in[15];
    const float* fc3_b  = (const float*)d_in[16];
    float* out = (float*)d_out;

    const int N = in_sizes[0] / IN_W;
    const int E = in_sizes[1] / 2;
    const int* src = ei;
    const int* dst = ei + E;

    float *aggr, *deg;
    __half *we, *h1h, *h1l, *h2h, *h2l, *k2h, *k2l, *k3;
    cudaGetSymbolAddress((void**)&we,   g_we);
    cudaGetSymbolAddress((void**)&aggr, g_aggr);
    cudaGetSymbolAddress((void**)&deg,  g_deg);
    cudaGetSymbolAddress((void**)&h1h,  g_h1h);
    cudaGetSymbolAddress((void**)&h1l,  g_h1l);
    cudaGetSymbolAddress((void**)&h2h,  g_h2h);
    cudaGetSymbolAddress((void**)&h2l,  g_h2l);
    cudaGetSymbolAddress((void**)&k2h,  g_k2h);
    cudaGetSymbolAddress((void**)&k2l,  g_k2l);
    cudaGetSymbolAddress((void**)&k3,   g_k3);

    static bool attr_done = false;
    if (!attr_done) {
        cudaFuncSetAttribute(mma_split_gemm<1>, cudaFuncAttributeMaxDynamicSharedMemorySize, SMEM_BYTES);
        cudaFuncSetAttribute(mma_split_gemm<0>, cudaFuncAttributeMaxDynamicSharedMemorySize, SMEM_BYTES);
        attr_done = true;
    }

    // launch order: GEMM3 at index 5 for the ncu -s 5 -c 1 window
    edge_fc1_kernel<<<(E + 1) / 2, 256>>>(ea, k1_w, k1_b, E);                            // 0
    split_kernel<<<((WK / 2) * WK + 255) / 256, 256>>>(k2_w, k2h, k2l, (WK / 2) * WK);   // 1
    convert_kernel<<<(WK * WN * WN + 255) / 256, 256>>>(k3_w, k3, WK * WN * WN);         // 2

    // GEMM2 (3-term fp16): h2 = relu(h1 @ k2 + b2), split fp16 out.  M=E, N=256, K=128
    {
        dim3 grid(WK / 128, (E + 127) / 128);
        mma_split_gemm<1><<<grid, 256, SMEM_BYTES>>>(h1h, h1l, k2h, k2l, k2_b,           // 3
                                                     h2h, h2l, nullptr, E, WK, WK / 2, 1, 1);
    }
    fc1_kernel<<<(N + 7) / 8, 256>>>(x, fc1_w, fc1_b, N);                                // 4
    // GEMM3 (2-term fp16): w_e = h2 @ k3 + b3, fp16 out.  M=E, N=1024, K=256
    {
        dim3 grid(WN * WN / 128, (E + 127) / 128);
        mma_split_gemm<0><<<grid, 256, SMEM_BYTES>>>(h2h, h2l, k3, nullptr, k3_b,        // 5
                                                     nullptr, nullptr, we, E, WN * WN, WK, 0, 2);
    }

    // in-degree + one-time aggr clear
    cudaMemsetAsync(deg, 0, (size_t)N * sizeof(float));
    cudaMemsetAsync(aggr, 0, (size_t)N * WN * sizeof(float));
    deg_kernel<<<(E + 255) / 256, 256>>>(dst, E);

    // message passing (combine zeroes aggr for the next depth)
    for (int d = 0; d < DEPTH; d++) {
        msg_scatter_kernel<<<(E + 7) / 8, 256>>>(src, dst, E);
        combine_kernel<<<(N + 7) / 8, 256>>>(root_w, conv_b, N, d != DEPTH - 1 ? 1 : 0);
    }

    // head
    head_kernel<<<N, 128>>>(fc2_w, fc2_b, fc3_w, fc3_b, out);
}

// round 8
// speedup vs baseline: 2.7100x; 1.2658x over previous
#include <cuda_runtime.h>
#include <cuda_fp16.h>
#include <cstdint>

// Problem constants (fixed by the dataset)
#define NN_NODES 10000
#define NN_EDGES 120000
#define IN_W 6
#define WN 32
#define WK 256
#define DEPTH 4

// ---------------- scratch (device globals; no allocation allowed) ----------
__device__ __half g_we [(size_t)NN_EDGES * WN * WN];   // per-edge weight mats (fp16)
__device__ __half g_h1h[(size_t)NN_EDGES * (WK / 2)];  // edge MLP hidden 1 (fp16 hi)
__device__ __half g_h1l[(size_t)NN_EDGES * (WK / 2)];  // edge MLP hidden 1 (fp16 lo)
__device__ __half g_h2 [(size_t)NN_EDGES * WK];        // edge MLP hidden 2 (fp16)
__device__ __half g_k2h[(WK / 2) * WK];
__device__ __half g_k2l[(WK / 2) * WK];
__device__ __half g_k3 [WK * WN * WN];                 // k3 fp16
__device__ float g_h   [(size_t)NN_NODES * WN];
__device__ float g_aggr[(size_t)NN_NODES * WN];
__device__ float g_deg [NN_NODES];

// ============================================================================
// fp16-split tensor-core GEMM: C = act(A@B + bias), fp16 output.
// TERMS=3: C ≈ Ah*Bh + Al*Bh + Ah*Bl  (split A and B)
// TERMS=1: C ≈ Ah*Bh                  (pure fp16; ~2.8e-4 operand rounding)
// Block tile 128x128, BK=32, 256 threads (8 warps, 2x4), warp tile 64x32.
// ============================================================================

#define SA_PAD 40
#define SB_PAD 136
#define AH_OFF 0
#define AL_OFF (128 * SA_PAD)
#define BH_OFF (2 * 128 * SA_PAD)
#define BL_OFF (BH_OFF + 32 * SB_PAD)
#define BUF_H  (BL_OFF + 32 * SB_PAD)
#define SMEM_BYTES (2 * BUF_H * 2)          // 75776 bytes

__device__ __forceinline__ void cp16(uint32_t dst, const void* src, int sbytes) {
    asm volatile("cp.async.cg.shared.global [%0], [%1], 16, %2;\n"
                 :: "r"(dst), "l"(src), "r"(sbytes));
}
__device__ __forceinline__ void ldsm_x4(uint32_t* r, uint32_t addr) {
    asm volatile("ldmatrix.sync.aligned.m8n8.x4.shared.b16 {%0,%1,%2,%3}, [%4];"
                 : "=r"(r[0]), "=r"(r[1]), "=r"(r[2]), "=r"(r[3]) : "r"(addr));
}
__device__ __forceinline__ void ldsm_x4t(uint32_t* r, uint32_t addr) {
    asm volatile("ldmatrix.sync.aligned.m8n8.x4.trans.shared.b16 {%0,%1,%2,%3}, [%4];"
                 : "=r"(r[0]), "=r"(r[1]), "=r"(r[2]), "=r"(r[3]) : "r"(addr));
}
__device__ __forceinline__ void mma16816(float* c, const uint32_t* a, uint32_t b0, uint32_t b1) {
    asm volatile("mma.sync.aligned.m16n8k16.row.col.f32.f16.f16.f32 "
                 "{%0,%1,%2,%3}, {%4,%5,%6,%7}, {%8,%9}, {%0,%1,%2,%3};"
                 : "+f"(c[0]), "+f"(c[1]), "+f"(c[2]), "+f"(c[3])
                 : "r"(a[0]), "r"(a[1]), "r"(a[2]), "r"(a[3]), "r"(b0), "r"(b1));
}

template<int TERMS>
__global__ __launch_bounds__(256, 2)
void mma_split_gemm(const __half* __restrict__ Ah, const __half* __restrict__ Al,
                    const __half* __restrict__ Bh, const __half* __restrict__ Bl,
                    const float* __restrict__ bias, __half* __restrict__ Cout,
                    int M, int N, int K, int doRelu)
{
    extern __shared__ __half smem[];
    const int tid  = threadIdx.x;
    const int lane = tid & 31;
    const int wid  = tid >> 5;
    const int bm = blockIdx.y * 128;
    const int bn = blockIdx.x * 128;
    const int warp_m = (wid & 1) * 64;
    const int warp_n = (wid >> 1) * 32;

    uint32_t su = (uint32_t)__cvta_generic_to_shared(smem);

    float C[4][4][4];
#pragma unroll
    for (int mt = 0; mt < 4; mt++)
#pragma unroll
        for (int nt = 0; nt < 4; nt++)
#pragma unroll
            for (int q = 0; q < 4; q++) C[mt][nt][q] = 0.f;

    const int nk = K / 32;

    auto load_tile = [&](int kt, int buf) {
        const int k0 = kt * 32;
        const uint32_t sbase = su + (uint32_t)buf * BUF_H * 2;
        // A hi: 512 chunks (128 rows x 4 16B-chunks)
#pragma unroll
        for (int t = 0; t < 2; t++) {
            int cid = tid + t * 256;
            int rr  = cid >> 2;
            int c8  = (cid & 3) * 8;
            int gr  = bm + rr;
            int ok  = (gr < M) ? 16 : 0;
            const __half* src = Ah + (size_t)(ok ? gr : 0) * K + k0 + c8;
            cp16(sbase + (uint32_t)(AH_OFF + rr * SA_PAD + c8) * 2, src, ok);
        }
        if (TERMS >= 2) {
#pragma unroll
            for (int t = 0; t < 2; t++) {
                int cid = tid + t * 256;
                int rr  = cid >> 2;
                int c8  = (cid & 3) * 8;
                int gr  = bm + rr;
                int ok  = (gr < M) ? 16 : 0;
                const __half* src = Al + (size_t)(ok ? gr : 0) * K + k0 + c8;
                cp16(sbase + (uint32_t)(AL_OFF + rr * SA_PAD + c8) * 2, src, ok);
            }
        }
        // B hi: 512 chunks (32 rows x 16 chunks)
#pragma unroll
        for (int t = 0; t < 2; t++) {
            int cid = tid + t * 256;
            int rr  = cid >> 4;
            int c8  = (cid & 15) * 8;
            const __half* src = Bh + (size_t)(k0 + rr) * N + bn + c8;
            cp16(sbase + (uint32_t)(BH_OFF + rr * SB_PAD + c8) * 2, src, 16);
        }
        if (TERMS == 3) {
#pragma unroll
            for (int t = 0; t < 2; t++) {
                int cid = tid + t * 256;
                int rr  = cid >> 4;
                int c8  = (cid & 15) * 8;
                const __half* src = Bl + (size_t)(k0 + rr) * N + bn + c8;
                cp16(sbase + (uint32_t)(BL_OFF + rr * SB_PAD + c8) * 2, src, 16);
            }
        }
    };

    load_tile(0, 0);
    asm volatile("cp.async.commit_group;\n" ::: "memory");

    for (int i = 0; i < nk; i++) {
        const int buf = i & 1;
        if (i + 1 < nk) {
            load_tile(i + 1, buf ^ 1);
            asm volatile("cp.async.commit_group;\n" ::: "memory");
            asm volatile("cp.async.wait_group 1;\n" ::: "memory");
        } else {
            asm volatile("cp.async.wait_group 0;\n" ::: "memory");
        }
        __syncthreads();

        const uint32_t aH = su + (uint32_t)(buf * BUF_H + AH_OFF) * 2;
        const uint32_t aL = su + (uint32_t)(buf * BUF_H + AL_OFF) * 2;
        const uint32_t bH = su + (uint32_t)(buf * BUF_H + BH_OFF) * 2;
        const uint32_t bL = su + (uint32_t)(buf * BUF_H + BL_OFF) * 2;

        const int arow = lane & 15;
        const int acol = (lane >> 4) * 8;
        // x4.trans B lane map
        const int bk  = ((lane >> 3) & 1) * 8 + (lane & 7);
        const int bn8 = (lane >> 4) * 8;

#pragma unroll
        for (int ks = 0; ks < 32; ks += 16) {
            uint32_t bh[2][4], bl[2][4];
#pragma unroll
            for (int ntp = 0; ntp < 2; ntp++) {
                uint32_t boff = (uint32_t)((ks + bk) * SB_PAD + warp_n + ntp * 16 + bn8) * 2;
                ldsm_x4t(bh[ntp], bH + boff);
                if (TERMS == 3) ldsm_x4t(bl[ntp], bL + boff);
            }
#pragma unroll
            for (int mt = 0; mt < 4; mt++) {
                uint32_t ah[4], al[4];
                uint32_t off = (uint32_t)((warp_m + mt * 16 + arow) * SA_PAD + ks + acol) * 2;
                ldsm_x4(ah, aH + off);
                if (TERMS >= 2) ldsm_x4(al, aL + off);
#pragma unroll
                for (int nt = 0; nt < 4; nt++) {
                    uint32_t b0 = bh[nt >> 1][(nt & 1) * 2];
                    uint32_t b1 = bh[nt >> 1][(nt & 1) * 2 + 1];
                    mma16816(C[mt][nt], ah, b0, b1);
                    if (TERMS >= 2) mma16816(C[mt][nt], al, b0, b1);
                    if (TERMS == 3) {
                        uint32_t c0 = bl[nt >> 1][(nt & 1) * 2];
                        uint32_t c1 = bl[nt >> 1][(nt & 1) * 2 + 1];
                        mma16816(C[mt][nt], ah, c0, c1);
                    }
                }
            }
        }
        __syncthreads();
    }

    // epilogue: bias + optional relu, fp16 out
#pragma unroll
    for (int mt = 0; mt < 4; mt++) {
#pragma unroll
        for (int nt = 0; nt < 4; nt++) {
            int r0  = bm + warp_m + mt * 16 + (lane >> 2);
            int col = bn + warp_n + nt * 8 + (lane & 3) * 2;
            float b0 = bias[col], b1 = bias[col + 1];
            float v0 = C[mt][nt][0] + b0;
            float v1 = C[mt][nt][1] + b1;
            float v2 = C[mt][nt][2] + b0;
            float v3 = C[mt][nt][3] + b1;
            if (doRelu) {
                v0 = fmaxf(v0, 0.f); v1 = fmaxf(v1, 0.f);
                v2 = fmaxf(v2, 0.f); v3 = fmaxf(v3, 0.f);
            }
            if (r0 < M) {
                __half2 p; p.x = __float2half(v0); p.y = __float2half(v1);
                *reinterpret_cast<__half2*>(&Cout[(size_t)r0 * N + col]) = p;
            }
            if (r0 + 8 < M) {
                __half2 p; p.x = __float2half(v2); p.y = __float2half(v3);
                *reinterpret_cast<__half2*>(&Cout[(size_t)(r0 + 8) * N + col]) = p;
            }
        }
    }
}

// ---------------- small kernels --------------------------------------------

__global__ void split_kernel(const float* __restrict__ in, __half* __restrict__ hi,
                             __half* __restrict__ lo, int n)
{
    int i = blockIdx.x * blockDim.x + threadIdx.x;
    if (i < n) {
        float v = in[i];
        __half h = __float2half(v);
        hi[i] = h;
        lo[i] = __float2half(v - __half2float(h));
    }
}

__global__ void convert_kernel(const float* __restrict__ in, __half* __restrict__ o, int n)
{
    int i = blockIdx.x * blockDim.x + threadIdx.x;
    if (i < n) o[i] = __float2half(in[i]);
}

// h1 = relu(ea @ k1_w + k1_b), written split. 256 threads = 2 edges per block.
__global__ __launch_bounds__(256)
void edge_fc1_kernel(const float* __restrict__ ea, const float* __restrict__ w,
                     const float* __restrict__ b, int E)
{
    int sub = threadIdx.x >> 7;
    int tid = threadIdx.x & 127;
    int e = blockIdx.x * 2 + sub;
    if (e >= E) return;
    __shared__ float a[2][IN_W];
    if (tid < IN_W) a[sub][tid] = ea[(size_t)e * IN_W + tid];
    __syncthreads();
    float acc = b[tid];
#pragma unroll
    for (int i = 0; i < IN_W; i++) acc = fmaf(a[sub][i], w[i * (WK / 2) + tid], acc);
    acc = fmaxf(acc, 0.f);
    __half h = __float2half(acc);
    g_h1h[(size_t)e * (WK / 2) + tid] = h;
    g_h1l[(size_t)e * (WK / 2) + tid] = __float2half(acc - __half2float(h));
}

__global__ void deg_kernel(const int* __restrict__ dst, int E)
{
    int e = blockIdx.x * blockDim.x + threadIdx.x;
    if (e < E) atomicAdd(&g_deg[dst[e]], 1.f);
}

__global__ __launch_bounds__(256)
void fc1_kernel(const float* __restrict__ x, const float* __restrict__ w,
                const float* __restrict__ b, int N)
{
    int warp = threadIdx.x >> 5, lane = threadIdx.x & 31;
    int n = blockIdx.x * 8 + warp;
    if (n >= N) return;
    float xv = (lane < IN_W) ? x[(size_t)n * IN_W + lane] : 0.f;
    float acc = b[lane];
#pragma unroll
    for (int i = 0; i < IN_W; i++) {
        float xi = __shfl_sync(0xffffffffu, xv, i);
        acc = fmaf(xi, w[i * WN + lane], acc);
    }
    g_h[(size_t)n * WN + lane] = acc;
}

// per-edge matvec msg = h[src] @ w_e (fp16), scattered to aggr[dst].
__global__ __launch_bounds__(256)
void msg_scatter_kernel(const int* __restrict__ src, const int* __restrict__ dst, int E)
{
    int warp = threadIdx.x >> 5, lane = threadIdx.x & 31;
    int e = blockIdx.x * 8 + warp;
    if (e >= E) return;
    int s = src[e], d = dst[e];
    int j = lane & 15;
    int r = lane >> 4;
    float hv = g_h[(size_t)s * WN + lane];
    const __half2* w2 = reinterpret_cast<const __half2*>(&g_we[(size_t)e * WN * WN]);
    float ax = 0.f, ay = 0.f;
#pragma unroll
    for (int i = 0; i < WN; i += 2) {
        float hi = __shfl_sync(0xffffffffu, hv, i + r);
        float2 wf = __half22float2(w2[(i + r) * 16 + j]);
        ax = fmaf(hi, wf.x, ax);
        ay = fmaf(hi, wf.y, ay);
    }
    ax += __shfl_xor_sync(0xffffffffu, ax, 16);
    ay += __shfl_xor_sync(0xffffffffu, ay, 16);
    if (lane < 16) {
        atomicAdd(&g_aggr[(size_t)d * WN + 2 * j],     ax);
        atomicAdd(&g_aggr[(size_t)d * WN + 2 * j + 1], ay);
    }
}

// h = [relu]( aggr/denom + h @ root_w + conv_b ); also zeroes aggr for next round
__global__ __launch_bounds__(256)
void combine_kernel(const float* __restrict__ root_w, const float* __restrict__ conv_b,
                    int N, int doRelu)
{
    __shared__ float rw[WN * WN];
    __shared__ float cb[WN];
    int tid = threadIdx.x;
    for (int i = tid; i < WN * WN; i += blockDim.x) rw[i] = root_w[i];
    if (tid < WN) cb[tid] = conv_b[tid];
    __syncthreads();

    int warp = tid >> 5, lane = tid & 31;
    int n = blockIdx.x * 8 + warp;
    if (n >= N) return;
    float hv = g_h[(size_t)n * WN + lane];
    float denom = fmaxf(g_deg[n], 1.f);
    float acc = g_aggr[(size_t)n * WN + lane] / denom + cb[lane];
    g_aggr[(size_t)n * WN + lane] = 0.f;
#pragma unroll
    for (int i = 0; i < WN; i++) {
        float hi = __shfl_sync(0xffffffffu, hv, i);
        acc = fmaf(hi, rw[i * WN + lane], acc);
    }
    if (doRelu) acc = fmaxf(acc, 0.f);
    g_h[(size_t)n * WN + lane] = acc;
}

__global__ __launch_bounds__(128)
void head_kernel(const float* __restrict__ fc2_w, const float* __restrict__ fc2_b,
                 const float* __restrict__ fc3_w, const float* __restrict__ fc3_b,
                 float* __restrict__ out)
{
    int n = blockIdx.x, tid = threadIdx.x;
    __shared__ float sh[WN];
    __shared__ float red[4];
    if (tid < WN) sh[tid] = g_h[(size_t)n * WN + tid];
    __syncthreads();
    float a = fc2_b[tid];
#pragma unroll
    for (int i = 0; i < WN; i++) a = fmaf(sh[i], fc2_w[i * 128 + tid], a);
    a = fmaxf(a, 0.f) * fc3_w[tid];
#pragma unroll
    for (int o = 16; o; o >>= 1) a += __shfl_xor_sync(0xffffffffu, a, o);
    if ((tid & 31) == 0) red[tid >> 5] = a;
    __syncthreads();
    if (tid == 0) out[n] = red[0] + red[1] + red[2] + red[3] + fc3_b[0];
}

// ---------------- launch ----------------------------------------------------
extern "C" void kernel_launch(void* const* d_in, const int* in_sizes, int n_in,
                              void* d_out, int out_size)
{
    const float* x      = (const float*)d_in[0];
    const int*   ei     = (const int*)  d_in[1];
    const float* ea     = (const float*)d_in[2];
    const float* fc1_w  = (const float*)d_in[3];
    const float* fc1_b  = (const float*)d_in[4];
    const float* k1_w   = (const float*)d_in[5];
    const float* k1_b   = (const float*)d_in[6];
    const float* k2_w   = (const float*)d_in[7];
    const float* k2_b   = (const float*)d_in[8];
    const float* k3_w   = (const float*)d_in[9];
    const float* k3_b   = (const float*)d_in[10];
    const float* root_w = (const float*)d_in[11];
    const float* conv_b = (const float*)d_in[12];
    const float* fc2_w  = (const float*)d_in[13];
    const float* fc2_b  = (const float*)d_in[14];
    const float* fc3_w  = (const float*)d_in[15];
    const float* fc3_b  = (const float*)d_in[16];
    float* out = (float*)d_out;

    const int N = in_sizes[0] / IN_W;
    const int E = in_sizes[1] / 2;
    const int* src = ei;
    const int* dst = ei + E;

    float *aggr, *deg;
    __half *we, *h1h, *h1l, *h2, *k2h, *k2l, *k3;
    cudaGetSymbolAddress((void**)&we,   g_we);
    cudaGetSymbolAddress((void**)&aggr, g_aggr);
    cudaGetSymbolAddress((void**)&deg,  g_deg);
    cudaGetSymbolAddress((void**)&h1h,  g_h1h);
    cudaGetSymbolAddress((void**)&h1l,  g_h1l);
    cudaGetSymbolAddress((void**)&h2,   g_h2);
    cudaGetSymbolAddress((void**)&k2h,  g_k2h);
    cudaGetSymbolAddress((void**)&k2l,  g_k2l);
    cudaGetSymbolAddress((void**)&k3,   g_k3);

    static bool attr_done = false;
    if (!attr_done) {
        cudaFuncSetAttribute(mma_split_gemm<3>, cudaFuncAttributeMaxDynamicSharedMemorySize, SMEM_BYTES);
        cudaFuncSetAttribute(mma_split_gemm<1>, cudaFuncAttributeMaxDynamicSharedMemorySize, SMEM_BYTES);
        attr_done = true;
    }

    // launch order: GEMM3 at index 5 for the ncu -s 5 -c 1 window
    edge_fc1_kernel<<<(E + 1) / 2, 256>>>(ea, k1_w, k1_b, E);                            // 0
    split_kernel<<<((WK / 2) * WK + 255) / 256, 256>>>(k2_w, k2h, k2l, (WK / 2) * WK);   // 1
    convert_kernel<<<(WK * WN * WN + 255) / 256, 256>>>(k3_w, k3, WK * WN * WN);         // 2

    // GEMM2 (3-term): h2 = relu(h1 @ k2 + b2), fp16 out.  M=E, N=256, K=128
    {
        dim3 grid(WK / 128, (E + 127) / 128);
        mma_split_gemm<3><<<grid, 256, SMEM_BYTES>>>(h1h, h1l, k2h, k2l, k2_b,           // 3
                                                     h2, E, WK, WK / 2, 1);
    }
    fc1_kernel<<<(N + 7) / 8, 256>>>(x, fc1_w, fc1_b, N);                                // 4
    // GEMM3 (1-term pure fp16): w_e = h2 @ k3 + b3, fp16 out.  M=E, N=1024, K=256
    {
        dim3 grid(WN * WN / 128, (E + 127) / 128);
        mma_split_gemm<1><<<grid, 256, SMEM_BYTES>>>(h2, nullptr, k3, nullptr, k3_b,     // 5
                                                     we, E, WN * WN, WK, 0);
    }

    // in-degree + one-time aggr clear
    cudaMemsetAsync(deg, 0, (size_t)N * sizeof(float));
    cudaMemsetAsync(aggr, 0, (size_t)N * WN * sizeof(float));
    deg_kernel<<<(E + 255) / 256, 256>>>(dst, E);

    // message passing (combine zeroes aggr for the next depth)
    for (int d = 0; d < DEPTH; d++) {
        msg_scatter_kernel<<<(E + 7) / 8, 256>>>(src, dst, E);
        combine_kernel<<<(N + 7) / 8, 256>>>(root_w, conv_b, N, d != DEPTH - 1 ? 1 : 0);
    }

    // head
    head_kernel<<<N, 128>>>(fc2_w, fc2_b, fc3_w, fc3_b, out);
}

// round 9
// speedup vs baseline: 2.8320x; 1.0450x over previous
#include <cuda_runtime.h>
#include <cuda_fp16.h>
#include <cstdint>

// Problem constants (fixed by the dataset)
#define NN_NODES 10000
#define NN_EDGES 120000
#define IN_W 6
#define WN 32
#define WK 256
#define DEPTH 4

// ---------------- scratch (device globals; no allocation allowed) ----------
__device__ __half g_we [(size_t)NN_EDGES * WN * WN];   // per-edge weight mats (fp16)
__device__ __half g_h1h[(size_t)NN_EDGES * (WK / 2)];  // edge MLP hidden 1 (fp16 hi)
__device__ __half g_h1l[(size_t)NN_EDGES * (WK / 2)];  // edge MLP hidden 1 (fp16 lo)
__device__ __half g_h2 [(size_t)NN_EDGES * WK];        // edge MLP hidden 2 (fp16)
__device__ __half g_k2 [(WK / 2) * WK];                // k2 fp16
__device__ __half g_k3 [WK * WN * WN];                 // k3 fp16
__device__ float g_h   [(size_t)NN_NODES * WN];
__device__ float g_aggr[(size_t)NN_NODES * WN];
__device__ float g_deg [NN_NODES];

// ============================================================================
// fp16-split tensor-core GEMM: C = act(A@B + bias), fp16 output.
// TERMS=3: C ≈ Ah*Bh + Al*Bh + Ah*Bl
// TERMS=2: C ≈ Ah*Bh + Al*Bh          (A split, B single)
// TERMS=1: C ≈ Ah*Bh                  (pure fp16)
// Block tile 128x128, BK=32, 256 threads (8 warps, 2x4), warp tile 64x32.
// ============================================================================

#define SA_PAD 40
#define SB_PAD 136
#define AH_OFF 0
#define AL_OFF (128 * SA_PAD)
#define BH_OFF (2 * 128 * SA_PAD)
#define BL_OFF (BH_OFF + 32 * SB_PAD)
#define BUF_H  (BL_OFF + 32 * SB_PAD)
#define SMEM_BYTES (2 * BUF_H * 2)          // 75776 bytes

__device__ __forceinline__ void cp16(uint32_t dst, const void* src, int sbytes) {
    asm volatile("cp.async.cg.shared.global [%0], [%1], 16, %2;\n"
                 :: "r"(dst), "l"(src), "r"(sbytes));
}
__device__ __forceinline__ void ldsm_x4(uint32_t* r, uint32_t addr) {
    asm volatile("ldmatrix.sync.aligned.m8n8.x4.shared.b16 {%0,%1,%2,%3}, [%4];"
                 : "=r"(r[0]), "=r"(r[1]), "=r"(r[2]), "=r"(r[3]) : "r"(addr));
}
__device__ __forceinline__ void ldsm_x4t(uint32_t* r, uint32_t addr) {
    asm volatile("ldmatrix.sync.aligned.m8n8.x4.trans.shared.b16 {%0,%1,%2,%3}, [%4];"
                 : "=r"(r[0]), "=r"(r[1]), "=r"(r[2]), "=r"(r[3]) : "r"(addr));
}
__device__ __forceinline__ void mma16816(float* c, const uint32_t* a, uint32_t b0, uint32_t b1) {
    asm volatile("mma.sync.aligned.m16n8k16.row.col.f32.f16.f16.f32 "
                 "{%0,%1,%2,%3}, {%4,%5,%6,%7}, {%8,%9}, {%0,%1,%2,%3};"
                 : "+f"(c[0]), "+f"(c[1]), "+f"(c[2]), "+f"(c[3])
                 : "r"(a[0]), "r"(a[1]), "r"(a[2]), "r"(a[3]), "r"(b0), "r"(b1));
}

template<int TERMS>
__global__ __launch_bounds__(256, 2)
void mma_split_gemm(const __half* __restrict__ Ah, const __half* __restrict__ Al,
                    const __half* __restrict__ Bh, const __half* __restrict__ Bl,
                    const float* __restrict__ bias, __half* __restrict__ Cout,
                    int M, int N, int K, int doRelu)
{
    extern __shared__ __half smem[];
    const int tid  = threadIdx.x;
    const int lane = tid & 31;
    const int wid  = tid >> 5;
    const int bm = blockIdx.y * 128;
    const int bn = blockIdx.x * 128;
    const int warp_m = (wid & 1) * 64;
    const int warp_n = (wid >> 1) * 32;

    uint32_t su = (uint32_t)__cvta_generic_to_shared(smem);

    float C[4][4][4];
#pragma unroll
    for (int mt = 0; mt < 4; mt++)
#pragma unroll
        for (int nt = 0; nt < 4; nt++)
#pragma unroll
            for (int q = 0; q < 4; q++) C[mt][nt][q] = 0.f;

    const int nk = K / 32;

    auto load_tile = [&](int kt, int buf) {
        const int k0 = kt * 32;
        const uint32_t sbase = su + (uint32_t)buf * BUF_H * 2;
#pragma unroll
        for (int t = 0; t < 2; t++) {
            int cid = tid + t * 256;
            int rr  = cid >> 2;
            int c8  = (cid & 3) * 8;
            int gr  = bm + rr;
            int ok  = (gr < M) ? 16 : 0;
            const __half* src = Ah + (size_t)(ok ? gr : 0) * K + k0 + c8;
            cp16(sbase + (uint32_t)(AH_OFF + rr * SA_PAD + c8) * 2, src, ok);
        }
        if (TERMS >= 2) {
#pragma unroll
            for (int t = 0; t < 2; t++) {
                int cid = tid + t * 256;
                int rr  = cid >> 2;
                int c8  = (cid & 3) * 8;
                int gr  = bm + rr;
                int ok  = (gr < M) ? 16 : 0;
                const __half* src = Al + (size_t)(ok ? gr : 0) * K + k0 + c8;
                cp16(sbase + (uint32_t)(AL_OFF + rr * SA_PAD + c8) * 2, src, ok);
            }
        }
#pragma unroll
        for (int t = 0; t < 2; t++) {
            int cid = tid + t * 256;
            int rr  = cid >> 4;
            int c8  = (cid & 15) * 8;
            const __half* src = Bh + (size_t)(k0 + rr) * N + bn + c8;
            cp16(sbase + (uint32_t)(BH_OFF + rr * SB_PAD + c8) * 2, src, 16);
        }
        if (TERMS == 3) {
#pragma unroll
            for (int t = 0; t < 2; t++) {
                int cid = tid + t * 256;
                int rr  = cid >> 4;
                int c8  = (cid & 15) * 8;
                const __half* src = Bl + (size_t)(k0 + rr) * N + bn + c8;
                cp16(sbase + (uint32_t)(BL_OFF + rr * SB_PAD + c8) * 2, src, 16);
            }
        }
    };

    load_tile(0, 0);
    asm volatile("cp.async.commit_group;\n" ::: "memory");

    for (int i = 0; i < nk; i++) {
        const int buf = i & 1;
        if (i + 1 < nk) {
            load_tile(i + 1, buf ^ 1);
            asm volatile("cp.async.commit_group;\n" ::: "memory");
            asm volatile("cp.async.wait_group 1;\n" ::: "memory");
        } else {
            asm volatile("cp.async.wait_group 0;\n" ::: "memory");
        }
        __syncthreads();

        const uint32_t aH = su + (uint32_t)(buf * BUF_H + AH_OFF) * 2;
        const uint32_t aL = su + (uint32_t)(buf * BUF_H + AL_OFF) * 2;
        const uint32_t bH = su + (uint32_t)(buf * BUF_H + BH_OFF) * 2;
        const uint32_t bL = su + (uint32_t)(buf * BUF_H + BL_OFF) * 2;

        const int arow = lane & 15;
        const int acol = (lane >> 4) * 8;
        const int bk  = ((lane >> 3) & 1) * 8 + (lane & 7);
        const int bn8 = (lane >> 4) * 8;

#pragma unroll
        for (int ks = 0; ks < 32; ks += 16) {
            uint32_t bh[2][4], bl[2][4];
#pragma unroll
            for (int ntp = 0; ntp < 2; ntp++) {
                uint32_t boff = (uint32_t)((ks + bk) * SB_PAD + warp_n + ntp * 16 + bn8) * 2;
                ldsm_x4t(bh[ntp], bH + boff);
                if (TERMS == 3) ldsm_x4t(bl[ntp], bL + boff);
            }
#pragma unroll
            for (int mt = 0; mt < 4; mt++) {
                uint32_t ah[4], al[4];
                uint32_t off = (uint32_t)((warp_m + mt * 16 + arow) * SA_PAD + ks + acol) * 2;
                ldsm_x4(ah, aH + off);
                if (TERMS >= 2) ldsm_x4(al, aL + off);
#pragma unroll
                for (int nt = 0; nt < 4; nt++) {
                    uint32_t b0 = bh[nt >> 1][(nt & 1) * 2];
                    uint32_t b1 = bh[nt >> 1][(nt & 1) * 2 + 1];
                    mma16816(C[mt][nt], ah, b0, b1);
                    if (TERMS >= 2) mma16816(C[mt][nt], al, b0, b1);
                    if (TERMS == 3) {
                        uint32_t c0 = bl[nt >> 1][(nt & 1) * 2];
                        uint32_t c1 = bl[nt >> 1][(nt & 1) * 2 + 1];
                        mma16816(C[mt][nt], ah, c0, c1);
                    }
                }
            }
        }
        __syncthreads();
    }

#pragma unroll
    for (int mt = 0; mt < 4; mt++) {
#pragma unroll
        for (int nt = 0; nt < 4; nt++) {
            int r0  = bm + warp_m + mt * 16 + (lane >> 2);
            int col = bn + warp_n + nt * 8 + (lane & 3) * 2;
            float b0 = bias[col], b1 = bias[col + 1];
            float v0 = C[mt][nt][0] + b0;
            float v1 = C[mt][nt][1] + b1;
            float v2 = C[mt][nt][2] + b0;
            float v3 = C[mt][nt][3] + b1;
            if (doRelu) {
                v0 = fmaxf(v0, 0.f); v1 = fmaxf(v1, 0.f);
                v2 = fmaxf(v2, 0.f); v3 = fmaxf(v3, 0.f);
            }
            if (r0 < M) {
                __half2 p; p.x = __float2half(v0); p.y = __float2half(v1);
                *reinterpret_cast<__half2*>(&Cout[(size_t)r0 * N + col]) = p;
            }
            if (r0 + 8 < M) {
                __half2 p; p.x = __float2half(v2); p.y = __float2half(v3);
                *reinterpret_cast<__half2*>(&Cout[(size_t)(r0 + 8) * N + col]) = p;
            }
        }
    }
}

// ---------------- small kernels --------------------------------------------

__global__ void convert_kernel(const float* __restrict__ in, __half* __restrict__ o, int n)
{
    int i = blockIdx.x * blockDim.x + threadIdx.x;
    if (i < n) o[i] = __float2half(in[i]);
}

// h1 = relu(ea @ k1_w + k1_b), written split. 256 threads = 2 edges per block.
__global__ __launch_bounds__(256)
void edge_fc1_kernel(const float* __restrict__ ea, const float* __restrict__ w,
                     const float* __restrict__ b, int E)
{
    int sub = threadIdx.x >> 7;
    int tid = threadIdx.x & 127;
    int e = blockIdx.x * 2 + sub;
    if (e >= E) return;
    __shared__ float a[2][IN_W];
    if (tid < IN_W) a[sub][tid] = ea[(size_t)e * IN_W + tid];
    __syncthreads();
    float acc = b[tid];
#pragma unroll
    for (int i = 0; i < IN_W; i++) acc = fmaf(a[sub][i], w[i * (WK / 2) + tid], acc);
    acc = fmaxf(acc, 0.f);
    __half h = __float2half(acc);
    g_h1h[(size_t)e * (WK / 2) + tid] = h;
    g_h1l[(size_t)e * (WK / 2) + tid] = __float2half(acc - __half2float(h));
}

__global__ void deg_kernel(const int* __restrict__ dst, int E)
{
    int e = blockIdx.x * blockDim.x + threadIdx.x;
    if (e < E) atomicAdd(&g_deg[dst[e]], 1.f);
}

__global__ __launch_bounds__(256)
void fc1_kernel(const float* __restrict__ x, const float* __restrict__ w,
                const float* __restrict__ b, int N)
{
    int warp = threadIdx.x >> 5, lane = threadIdx.x & 31;
    int n = blockIdx.x * 8 + warp;
    if (n >= N) return;
    float xv = (lane < IN_W) ? x[(size_t)n * IN_W + lane] : 0.f;
    float acc = b[lane];
#pragma unroll
    for (int i = 0; i < IN_W; i++) {
        float xi = __shfl_sync(0xffffffffu, xv, i);
        acc = fmaf(xi, w[i * WN + lane], acc);
    }
    g_h[(size_t)n * WN + lane] = acc;
}

// per-edge matvec msg = h[src] @ w_e (fp16), scattered to aggr[dst].
// uint4 path: lane l loads 4x16B covering rows (l>>2)+8k, col-group l&3;
// butterfly-reduce over the 8 lanes sharing a col-group; 1 atomic per lane.
__global__ __launch_bounds__(256)
void msg_scatter_kernel(const int* __restrict__ src, const int* __restrict__ dst, int E)
{
    int warp = threadIdx.x >> 5, lane = threadIdx.x & 31;
    int e = blockIdx.x * 8 + warp;
    if (e >= E) return;
    int s = src[e], d = dst[e];
    float hv = g_h[(size_t)s * WN + lane];
    const uint4* w4 = reinterpret_cast<const uint4*>(&g_we[(size_t)e * WN * WN]);
    // 4 independent 16B loads, issued up front
    uint4 q0 = w4[lane];
    uint4 q1 = w4[lane + 32];
    uint4 q2 = w4[lane + 64];
    uint4 q3 = w4[lane + 96];
    const int rbase = lane >> 2;     // row within 8-row group
    float acc[8];
#pragma unroll
    for (int j = 0; j < 8; j++) acc[j] = 0.f;

    auto accum = [&](const uint4& q, int k) {
        float hk = __shfl_sync(0xffffffffu, hv, rbase + 8 * k);
        const __half2* hp = reinterpret_cast<const __half2*>(&q);
#pragma unroll
        for (int p = 0; p < 4; p++) {
            float2 wf = __half22float2(hp[p]);
            acc[2 * p]     = fmaf(hk, wf.x, acc[2 * p]);
            acc[2 * p + 1] = fmaf(hk, wf.y, acc[2 * p + 1]);
        }
    };
    accum(q0, 0); accum(q1, 1); accum(q2, 2); accum(q3, 3);

    // reduce over the 8 lanes with the same col-group (bits 2..4 of lane)
#pragma unroll
    for (int m = 4; m <= 16; m <<= 1)
#pragma unroll
        for (int j = 0; j < 8; j++)
            acc[j] += __shfl_xor_sync(0xffffffffu, acc[j], m);

    // lane l writes col 8*(l&3) + (l>>2)
    atomicAdd(&g_aggr[(size_t)d * WN + 8 * (lane & 3) + rbase], acc[rbase]);
}

// h = [relu]( aggr/denom + h @ root_w + conv_b ); also zeroes aggr for next round
__global__ __launch_bounds__(256)
void combine_kernel(const float* __restrict__ root_w, const float* __restrict__ conv_b,
                    int N, int doRelu)
{
    __shared__ float rw[WN * WN];
    __shared__ float cb[WN];
    int tid = threadIdx.x;
    for (int i = tid; i < WN * WN; i += blockDim.x) rw[i] = root_w[i];
    if (tid < WN) cb[tid] = conv_b[tid];
    __syncthreads();

    int warp = tid >> 5, lane = tid & 31;
    int n = blockIdx.x * 8 + warp;
    if (n >= N) return;
    float hv = g_h[(size_t)n * WN + lane];
    float denom = fmaxf(g_deg[n], 1.f);
    float acc = g_aggr[(size_t)n * WN + lane] / denom + cb[lane];
    g_aggr[(size_t)n * WN + lane] = 0.f;
#pragma unroll
    for (int i = 0; i < WN; i++) {
        float hi = __shfl_sync(0xffffffffu, hv, i);
        acc = fmaf(hi, rw[i * WN + lane], acc);
    }
    if (doRelu) acc = fmaxf(acc, 0.f);
    g_h[(size_t)n * WN + lane] = acc;
}

__global__ __launch_bounds__(128)
void head_kernel(const float* __restrict__ fc2_w, const float* __restrict__ fc2_b,
                 const float* __restrict__ fc3_w, const float* __restrict__ fc3_b,
                 float* __restrict__ out)
{
    int n = blockIdx.x, tid = threadIdx.x;
    __shared__ float sh[WN];
    __shared__ float red[4];
    if (tid < WN) sh[tid] = g_h[(size_t)n * WN + tid];
    __syncthreads();
    float a = fc2_b[tid];
#pragma unroll
    for (int i = 0; i < WN; i++) a = fmaf(sh[i], fc2_w[i * 128 + tid], a);
    a = fmaxf(a, 0.f) * fc3_w[tid];
#pragma unroll
    for (int o = 16; o; o >>= 1) a += __shfl_xor_sync(0xffffffffu, a, o);
    if ((tid & 31) == 0) red[tid >> 5] = a;
    __syncthreads();
    if (tid == 0) out[n] = red[0] + red[1] + red[2] + red[3] + fc3_b[0];
}

// ---------------- launch ----------------------------------------------------
extern "C" void kernel_launch(void* const* d_in, const int* in_sizes, int n_in,
                              void* d_out, int out_size)
{
    const float* x      = (const float*)d_in[0];
    const int*   ei     = (const int*)  d_in[1];
    const float* ea     = (const float*)d_in[2];
    const float* fc1_w  = (const float*)d_in[3];
    const float* fc1_b  = (const float*)d_in[4];
    const float* k1_w   = (const float*)d_in[5];
    const float* k1_b   = (const float*)d_in[6];
    const float* k2_w   = (const float*)d_in[7];
    const float* k2_b   = (const float*)d_in[8];
    const float* k3_w   = (const float*)d_in[9];
    const float* k3_b   = (const float*)d_in[10];
    const float* root_w = (const float*)d_in[11];
    const float* conv_b = (const float*)d_in[12];
    const float* fc2_w  = (const float*)d_in[13];
    const float* fc2_b  = (const float*)d_in[14];
    const float* fc3_w  = (const float*)d_in[15];
    const float* fc3_b  = (const float*)d_in[16];
    float* out = (float*)d_out;

    const int N = in_sizes[0] / IN_W;
    const int E = in_sizes[1] / 2;
    const int* src = ei;
    const int* dst = ei + E;

    float *aggr, *deg;
    __half *we, *h1h, *h1l, *h2, *k2, *k3;
    cudaGetSymbolAddress((void**)&we,   g_we);
    cudaGetSymbolAddress((void**)&aggr, g_aggr);
    cudaGetSymbolAddress((void**)&deg,  g_deg);
    cudaGetSymbolAddress((void**)&h1h,  g_h1h);
    cudaGetSymbolAddress((void**)&h1l,  g_h1l);
    cudaGetSymbolAddress((void**)&h2,   g_h2);
    cudaGetSymbolAddress((void**)&k2,   g_k2);
    cudaGetSymbolAddress((void**)&k3,   g_k3);

    static bool attr_done = false;
    if (!attr_done) {
        cudaFuncSetAttribute(mma_split_gemm<2>, cudaFuncAttributeMaxDynamicSharedMemorySize, SMEM_BYTES);
        cudaFuncSetAttribute(mma_split_gemm<1>, cudaFuncAttributeMaxDynamicSharedMemorySize, SMEM_BYTES);
        attr_done = true;
    }

    // launch order: GEMM3 at index 5 for the ncu -s 5 -c 1 window
    edge_fc1_kernel<<<(E + 1) / 2, 256>>>(ea, k1_w, k1_b, E);                            // 0
    convert_kernel<<<((WK / 2) * WK + 255) / 256, 256>>>(k2_w, k2, (WK / 2) * WK);       // 1
    convert_kernel<<<(WK * WN * WN + 255) / 256, 256>>>(k3_w, k3, WK * WN * WN);         // 2

    // GEMM2 (2-term): h2 = relu(h1 @ k2 + b2), fp16 out.  M=E, N=256, K=128
    {
        dim3 grid(WK / 128, (E + 127) / 128);
        mma_split_gemm<2><<<grid, 256, SMEM_BYTES>>>(h1h, h1l, k2, nullptr, k2_b,        // 3
                                                     h2, E, WK, WK / 2, 1);
    }
    fc1_kernel<<<(N + 7) / 8, 256>>>(x, fc1_w, fc1_b, N);                                // 4
    // GEMM3 (1-term pure fp16): w_e = h2 @ k3 + b3, fp16 out.  M=E, N=1024, K=256
    {
        dim3 grid(WN * WN / 128, (E + 127) / 128);
        mma_split_gemm<1><<<grid, 256, SMEM_BYTES>>>(h2, nullptr, k3, nullptr, k3_b,     // 5
                                                     we, E, WN * WN, WK, 0);
    }

    // in-degree + one-time aggr clear
    cudaMemsetAsync(deg, 0, (size_t)N * sizeof(float));
    cudaMemsetAsync(aggr, 0, (size_t)N * WN * sizeof(float));
    deg_kernel<<<(E + 255) / 256, 256>>>(dst, E);

    // message passing (combine zeroes aggr for the next depth)
    for (int d = 0; d < DEPTH; d++) {
        msg_scatter_kernel<<<(E + 7) / 8, 256>>>(src, dst, E);
        combine_kernel<<<(N + 7) / 8, 256>>>(root_w, conv_b, N, d != DEPTH - 1 ? 1 : 0);
    }

    // head
    head_kernel<<<N, 128>>>(fc2_w, fc2_b, fc3_w, fc3_b, out);
}